// round 1
// baseline (speedup 1.0000x reference)
#include <cuda_runtime.h>
#include <math.h>
#include <stdint.h>

// Problem constants (fixed by the dataset)
#define BB   64
#define SS   2048
#define HH   512
#define MM   (BB * SS)          // 131072 rows
#define NTILES 8                // HH / BN

// GEMM tiling
#define BM 128
#define BN 64
#define BK 16
#define TM 8
#define TN 4

#define SCHUNK 256              // pool s-chunk
#define NCHUNK (SS / SCHUNK)    // 8

// Scratch (static device memory; no allocations allowed)
__device__ float g_part[NTILES * MM];        // per-N-tile partial scores, 4 MB
__device__ float g_attn[MM];                 // final attention weights, 512 KB
__device__ float g_pout[BB * NCHUNK * HH];   // pooling partials, 1 MB

// ---------------------------------------------------------------------------
// Kernel 1: fused GEMM + tanh-dot epilogue.
//   z[m, n] = sum_k X[m,k] * W[k,n]
//   g_part[ntile, m] = sum_{n in tile} tanh(z[m,n] + bias[n]) * w_attn[n]
// ---------------------------------------------------------------------------
__global__ __launch_bounds__(256) void gemm_score_kernel(
    const float* __restrict__ A,      // [MM, HH]
    const float* __restrict__ W,      // [HH, HH]
    const float* __restrict__ bias,   // [HH]
    const float* __restrict__ wat)    // [HH]
{
    __shared__ float As[BK][BM + 4];  // transposed A tile (+pad: kills store conflicts)
    __shared__ float Bs[BK][BN];

    const int m0  = blockIdx.y * BM;
    const int n0  = blockIdx.x * BN;
    const int tid = threadIdx.x;
    const int tx  = tid & 15;         // 0..15 -> N
    const int ty  = tid >> 4;         // 0..15 -> M

    float acc[TM][TN] = {};

    for (int k0 = 0; k0 < HH; k0 += BK) {
        // Load A tile (128x16) as 512 float4, transposed into As[k][m]
        #pragma unroll
        for (int t = 0; t < 2; t++) {
            int idx = tid + t * 256;
            int m   = idx >> 2;       // 0..127
            int kq  = idx & 3;        // 0..3
            float4 v = *reinterpret_cast<const float4*>(
                &A[(size_t)(m0 + m) * HH + k0 + kq * 4]);
            As[kq * 4 + 0][m] = v.x;
            As[kq * 4 + 1][m] = v.y;
            As[kq * 4 + 2][m] = v.z;
            As[kq * 4 + 3][m] = v.w;
        }
        // Load B tile (16x64) as 256 float4
        {
            int k  = tid >> 4;        // 0..15
            int nq = tid & 15;        // 0..15
            *reinterpret_cast<float4*>(&Bs[k][nq * 4]) =
                *reinterpret_cast<const float4*>(
                    &W[(size_t)(k0 + k) * HH + n0 + nq * 4]);
        }
        __syncthreads();

        #pragma unroll
        for (int kk = 0; kk < BK; kk++) {
            float a[TM], b[TN];
            #pragma unroll
            for (int i = 0; i < TM; i++) a[i] = As[kk][ty * TM + i];
            #pragma unroll
            for (int j = 0; j < TN; j++) b[j] = Bs[kk][tx * TN + j];
            #pragma unroll
            for (int i = 0; i < TM; i++)
                #pragma unroll
                for (int j = 0; j < TN; j++)
                    acc[i][j] = fmaf(a[i], b[j], acc[i][j]);
        }
        __syncthreads();
    }

    // Epilogue: s_partial[row] = sum_n tanh(acc + bias[n]) * w[n] over this N tile
    float bv[TN], wv[TN];
    #pragma unroll
    for (int j = 0; j < TN; j++) {
        bv[j] = bias[n0 + tx * TN + j];
        wv[j] = wat [n0 + tx * TN + j];
    }
    #pragma unroll
    for (int i = 0; i < TM; i++) {
        float s = 0.f;
        #pragma unroll
        for (int j = 0; j < TN; j++)
            s += tanhf(acc[i][j] + bv[j]) * wv[j];
        // reduce across the 16 tx lanes (contiguous 16-lane segments of the warp)
        #pragma unroll
        for (int off = 8; off > 0; off >>= 1)
            s += __shfl_down_sync(0xFFFFFFFFu, s, off, 16);
        if (tx == 0)
            g_part[(size_t)blockIdx.x * MM + m0 + ty * TM + i] = s;
    }
}

// ---------------------------------------------------------------------------
// Kernel 2: softmax over full sequence, then mask + renormalize.
//   attn = exp(s - max) * mask / (sum_masked_exp + 1e-6 * sum_all_exp)
// (equivalent to: softmax, *mask, /(sum+1e-6))
// ---------------------------------------------------------------------------
__global__ __launch_bounds__(256) void softmax_kernel(const int* __restrict__ seqlen)
{
    __shared__ float sc[SS];
    __shared__ float red[256];
    __shared__ float red2[256];

    const int b   = blockIdx.x;
    const int tid = threadIdx.x;
    const int len = seqlen[b];

    // gather partial scores (fixed summation order -> deterministic)
    for (int s = tid; s < SS; s += 256) {
        float v = 0.f;
        #pragma unroll
        for (int j = 0; j < NTILES; j++)
            v += g_part[(size_t)j * MM + (size_t)b * SS + s];
        sc[s] = v;
    }
    __syncthreads();

    // block max
    float m = -INFINITY;
    for (int s = tid; s < SS; s += 256) m = fmaxf(m, sc[s]);
    red[tid] = m;
    __syncthreads();
    for (int o = 128; o > 0; o >>= 1) {
        if (tid < o) red[tid] = fmaxf(red[tid], red[tid + o]);
        __syncthreads();
    }
    m = red[0];
    __syncthreads();

    // sums: z over all, zm over masked
    float z = 0.f, zm = 0.f;
    for (int s = tid; s < SS; s += 256) {
        float e = expf(sc[s] - m);
        z += e;
        if (s < len) zm += e;
    }
    red[tid] = z; red2[tid] = zm;
    __syncthreads();
    for (int o = 128; o > 0; o >>= 1) {
        if (tid < o) { red[tid] += red[tid + o]; red2[tid] += red2[tid + o]; }
        __syncthreads();
    }
    z = red[0]; zm = red2[0];

    const float inv = 1.f / (zm + 1e-6f * z);
    for (int s = tid; s < SS; s += 256) {
        float e = (s < len) ? expf(sc[s] - m) * inv : 0.f;
        g_attn[(size_t)b * SS + s] = e;
    }
}

// ---------------------------------------------------------------------------
// Kernel 3: pooling partials. grid (BB, NCHUNK), block = HH threads.
//   g_pout[b, c, h] = sum_{s in chunk, s < len} X[b,s,h] * attn[b,s]
// Skips X reads for fully-masked chunks (attn there is exactly 0).
// ---------------------------------------------------------------------------
__global__ __launch_bounds__(HH) void pool_kernel(
    const float* __restrict__ X, const int* __restrict__ seqlen)
{
    const int b  = blockIdx.x;
    const int c  = blockIdx.y;
    const int h  = threadIdx.x;
    const int s0 = c * SCHUNK;
    const int len = seqlen[b];

    __shared__ float at[SCHUNK];
    if (h < SCHUNK) at[h] = g_attn[(size_t)b * SS + s0 + h];
    __syncthreads();

    float acc = 0.f;
    int end = len - s0;
    if (end > SCHUNK) end = SCHUNK;
    if (end > 0) {
        const float* xp = &X[((size_t)b * SS + s0) * HH + h];
        #pragma unroll 8
        for (int s = 0; s < end; s++)
            acc = fmaf(xp[(size_t)s * HH], at[s], acc);
    }
    g_pout[((size_t)b * NCHUNK + c) * HH + h] = acc;
}

// ---------------------------------------------------------------------------
// Kernel 4: reduce pooling partials -> out[b, h]
// ---------------------------------------------------------------------------
__global__ __launch_bounds__(256) void reduce_out_kernel(float* __restrict__ out)
{
    int i = blockIdx.x * blockDim.x + threadIdx.x;
    if (i >= BB * HH) return;
    int b = i / HH, h = i % HH;
    float v = 0.f;
    #pragma unroll
    for (int c = 0; c < NCHUNK; c++)
        v += g_pout[((size_t)b * NCHUNK + c) * HH + h];
    out[i] = v;
}

// ---------------------------------------------------------------------------
extern "C" void kernel_launch(void* const* d_in, const int* in_sizes, int n_in,
                              void* d_out, int out_size)
{
    const float* X      = (const float*)d_in[0];  // [B,S,H]
    const int*   seqlen = (const int*)  d_in[1];  // [B]
    const float* W      = (const float*)d_in[2];  // [H,H]
    const float* bias   = (const float*)d_in[3];  // [H]
    const float* wat    = (const float*)d_in[4];  // [H,1]
    float*       out    = (float*)d_out;          // [B,H]

    dim3 ggemm(HH / BN, MM / BM);                 // (8, 1024)
    gemm_score_kernel<<<ggemm, 256>>>(X, W, bias, wat);

    softmax_kernel<<<BB, 256>>>(seqlen);

    dim3 gpool(BB, NCHUNK);                       // (64, 8)
    pool_kernel<<<gpool, HH>>>(X, seqlen);

    reduce_out_kernel<<<(BB * HH + 255) / 256, 256>>>(out);
}

// round 3
// speedup vs baseline: 1.7417x; 1.7417x over previous
#include <cuda_runtime.h>
#include <cuda_bf16.h>
#include <math.h>
#include <stdint.h>

// ---------------- problem constants ----------------
#define BB 64
#define SS 2048
#define HH 512
#define MM (BB * SS)            // 131072 rows
#define BM 128
#define BN 128
#define BK 32
#define NKC (HH / BK)           // 16 k-chunks
#define NT  (HH / BN)           // 4 n-tiles

#define SCHUNK 256
#define NCHUNK (SS / SCHUNK)    // 8

// SMEM layout (bytes). Rows padded to 40 bf16 (80 B) -> conflict-free frags.
#define AHI   0
#define ALO   10240
#define BHI   20480
#define BLO   30720
#define STAGE 40960
#define REDOFF (2 * STAGE)      // 81920
#define SMTOTAL (REDOFF + 128 * 4 * 4)   // 83968

// ---------------- scratch (static device mem) ----------------
__device__ float g_part[NT * MM];
__device__ float g_attn[MM];
__device__ float g_pout[BB * NCHUNK * HH];
__device__ __nv_bfloat16 g_Whi[HH * HH];   // Wt[n,k] = W[k,n], hi split
__device__ __nv_bfloat16 g_Wlo[HH * HH];   // lo split

// ---------------- helpers ----------------
__device__ __forceinline__ uint32_t smem_u32(const void* p) {
    uint32_t a;
    asm("{ .reg .u64 t; cvta.to.shared.u64 t, %1; cvt.u32.u64 %0, t; }"
        : "=r"(a) : "l"(p));
    return a;
}
__device__ __forceinline__ void cpa16(uint32_t dst, const void* src) {
    asm volatile("cp.async.cg.shared.global [%0], [%1], 16;"
                 :: "r"(dst), "l"(src) : "memory");
}
__device__ __forceinline__ void mma_bf16(float* d, const uint32_t* a, const uint32_t* b) {
    asm volatile("mma.sync.aligned.m16n8k16.row.col.f32.bf16.bf16.f32 "
                 "{%0,%1,%2,%3}, {%4,%5,%6,%7}, {%8,%9}, {%0,%1,%2,%3};"
                 : "+f"(d[0]), "+f"(d[1]), "+f"(d[2]), "+f"(d[3])
                 : "r"(a[0]), "r"(a[1]), "r"(a[2]), "r"(a[3]),
                   "r"(b[0]), "r"(b[1]));
}
__device__ __forceinline__ uint32_t pack_bf2(__nv_bfloat16 x, __nv_bfloat16 y) {
    return (uint32_t)__bfloat16_as_ushort(x)
         | ((uint32_t)__bfloat16_as_ushort(y) << 16);
}

// ---------------------------------------------------------------------------
// W prep: transpose + bf16 hi/lo split.  Wt[n,k] = W[k,n]
// ---------------------------------------------------------------------------
__global__ void prep_w(const float* __restrict__ W) {
    __shared__ float t[32][33];
    int n0 = blockIdx.x * 32, k0 = blockIdx.y * 32;
    int tx = threadIdx.x, ty = threadIdx.y;      // 32 x 8
    #pragma unroll
    for (int r = 0; r < 32; r += 8)
        t[ty + r][tx] = W[(size_t)(k0 + ty + r) * HH + n0 + tx];
    __syncthreads();
    #pragma unroll
    for (int r = 0; r < 32; r += 8) {
        int n = n0 + ty + r, k = k0 + tx;
        float x = t[tx][ty + r];
        __nv_bfloat16 h = __float2bfloat16_rn(x);
        g_Whi[(size_t)n * HH + k] = h;
        g_Wlo[(size_t)n * HH + k] = __float2bfloat16_rn(x - __bfloat162float(h));
    }
}

// ---------------------------------------------------------------------------
// Split-bf16 HMMA GEMM + fused tanh-dot epilogue.
// grid (NT, MM/BM), 256 threads (8 warps, 2M x 4N, warp tile 64x32).
// ---------------------------------------------------------------------------
__global__ __launch_bounds__(256) void gemm_score_mma(
    const float* __restrict__ A, const float* __restrict__ bias,
    const float* __restrict__ wat)
{
    extern __shared__ char sm[];
    const uint32_t sbase = smem_u32(sm);
    const int tid = threadIdx.x, lane = tid & 31, wid = tid >> 5;
    const int g = lane >> 2, tig = lane & 3;
    const int wm = wid >> 2, wn = wid & 3;
    const int m0 = blockIdx.y * BM, n0 = blockIdx.x * BN;

    const int arow = tid >> 1;            // 0..127
    const int af   = (tid & 1) * 4;       // float4 index base (0 or 4)

    float acc[4][4][4] = {};
    float4 rA[4];

    // ---- prologue: chunk 0 ----
    {
        const float* p = &A[(size_t)(m0 + arow) * HH + af * 4];
        #pragma unroll
        for (int q = 0; q < 4; q++) rA[q] = *(const float4*)(p + q * 4);
        #pragma unroll
        for (int t = 0; t < 4; t++) {
            int i = tid + t * 256;
            int hl = i >> 9, r = (i >> 2) & 127, seg = i & 3;
            const __nv_bfloat16* src =
                (hl ? g_Wlo : g_Whi) + (size_t)(n0 + r) * HH + seg * 8;
            cpa16(sbase + (hl ? BLO : BHI) + r * 80 + seg * 16, src);
        }
        asm volatile("cp.async.commit_group;" ::: "memory");
        // store A chunk 0 (split hi/lo)
        #pragma unroll
        for (int q = 0; q < 4; q++) {
            float4 v = rA[q];
            __nv_bfloat16 h0 = __float2bfloat16_rn(v.x), h1 = __float2bfloat16_rn(v.y);
            __nv_bfloat16 h2 = __float2bfloat16_rn(v.z), h3 = __float2bfloat16_rn(v.w);
            uint2 hp = make_uint2(pack_bf2(h0, h1), pack_bf2(h2, h3));
            uint2 lp = make_uint2(
                pack_bf2(__float2bfloat16_rn(v.x - __bfloat162float(h0)),
                         __float2bfloat16_rn(v.y - __bfloat162float(h1))),
                pack_bf2(__float2bfloat16_rn(v.z - __bfloat162float(h2)),
                         __float2bfloat16_rn(v.w - __bfloat162float(h3))));
            int off = arow * 80 + (af + q) * 8;
            *(uint2*)(sm + AHI + off) = hp;
            *(uint2*)(sm + ALO + off) = lp;
        }
        asm volatile("cp.async.wait_group 0;" ::: "memory");
        __syncthreads();
    }

    for (int c = 0; c < NKC; c++) {
        const int pb = c & 1, nb = pb ^ 1;
        if (c + 1 < NKC) {
            // prefetch chunk c+1
            const float* p = &A[(size_t)(m0 + arow) * HH + (c + 1) * BK + af * 4];
            #pragma unroll
            for (int q = 0; q < 4; q++) rA[q] = *(const float4*)(p + q * 4);
            #pragma unroll
            for (int t = 0; t < 4; t++) {
                int i = tid + t * 256;
                int hl = i >> 9, r = (i >> 2) & 127, seg = i & 3;
                const __nv_bfloat16* src =
                    (hl ? g_Wlo : g_Whi) + (size_t)(n0 + r) * HH + (c + 1) * BK + seg * 8;
                cpa16(sbase + nb * STAGE + (hl ? BLO : BHI) + r * 80 + seg * 16, src);
            }
            asm volatile("cp.async.commit_group;" ::: "memory");
        }

        // ---- compute on buffer pb ----
        {
            const char* bs = sm + pb * STAGE;
            #pragma unroll
            for (int ks = 0; ks < 2; ks++) {
                const int co = ks * 32 + tig * 4;   // column byte offset
                uint32_t bh[4][2], bl[4][2];
                #pragma unroll
                for (int ni = 0; ni < 4; ni++) {
                    const char* bp = bs + (wn * 32 + ni * 8 + g) * 80 + co;
                    bh[ni][0] = *(const uint32_t*)(bp + BHI);
                    bh[ni][1] = *(const uint32_t*)(bp + BHI + 16);
                    bl[ni][0] = *(const uint32_t*)(bp + BLO);
                    bl[ni][1] = *(const uint32_t*)(bp + BLO + 16);
                }
                #pragma unroll
                for (int mi = 0; mi < 4; mi++) {
                    const char* ap = bs + (wm * 64 + mi * 16 + g) * 80 + co;
                    uint32_t ah[4], al[4];
                    ah[0] = *(const uint32_t*)(ap + AHI);
                    ah[1] = *(const uint32_t*)(ap + AHI + 640);
                    ah[2] = *(const uint32_t*)(ap + AHI + 16);
                    ah[3] = *(const uint32_t*)(ap + AHI + 656);
                    al[0] = *(const uint32_t*)(ap + ALO);
                    al[1] = *(const uint32_t*)(ap + ALO + 640);
                    al[2] = *(const uint32_t*)(ap + ALO + 16);
                    al[3] = *(const uint32_t*)(ap + ALO + 656);
                    #pragma unroll
                    for (int ni = 0; ni < 4; ni++) {
                        mma_bf16(acc[mi][ni], ah, bh[ni]);
                        mma_bf16(acc[mi][ni], ah, bl[ni]);
                        mma_bf16(acc[mi][ni], al, bh[ni]);
                    }
                }
            }
        }

        if (c + 1 < NKC) {
            // store prefetched A into buffer nb
            #pragma unroll
            for (int q = 0; q < 4; q++) {
                float4 v = rA[q];
                __nv_bfloat16 h0 = __float2bfloat16_rn(v.x), h1 = __float2bfloat16_rn(v.y);
                __nv_bfloat16 h2 = __float2bfloat16_rn(v.z), h3 = __float2bfloat16_rn(v.w);
                uint2 hp = make_uint2(pack_bf2(h0, h1), pack_bf2(h2, h3));
                uint2 lp = make_uint2(
                    pack_bf2(__float2bfloat16_rn(v.x - __bfloat162float(h0)),
                             __float2bfloat16_rn(v.y - __bfloat162float(h1))),
                    pack_bf2(__float2bfloat16_rn(v.z - __bfloat162float(h2)),
                             __float2bfloat16_rn(v.w - __bfloat162float(h3))));
                int off = arow * 80 + (af + q) * 8;
                *(uint2*)(sm + nb * STAGE + AHI + off) = hp;
                *(uint2*)(sm + nb * STAGE + ALO + off) = lp;
            }
            asm volatile("cp.async.wait_group 0;" ::: "memory");
            __syncthreads();
        }
    }

    // ---- epilogue: tanh(z + b) * w, reduced over this CTA's 128 columns ----
    float* red = (float*)(sm + REDOFF);
    #pragma unroll
    for (int mi = 0; mi < 4; mi++) {
        float s0 = 0.f, s1 = 0.f;
        #pragma unroll
        for (int ni = 0; ni < 4; ni++) {
            int col = n0 + wn * 32 + ni * 8 + tig * 2;
            float2 bb = *(const float2*)&bias[col];
            float2 ww = *(const float2*)&wat[col];
            s0 += tanhf(acc[mi][ni][0] + bb.x) * ww.x
                + tanhf(acc[mi][ni][1] + bb.y) * ww.y;
            s1 += tanhf(acc[mi][ni][2] + bb.x) * ww.x
                + tanhf(acc[mi][ni][3] + bb.y) * ww.y;
        }
        s0 += __shfl_down_sync(0xFFFFFFFFu, s0, 2, 4);
        s0 += __shfl_down_sync(0xFFFFFFFFu, s0, 1, 4);
        s1 += __shfl_down_sync(0xFFFFFFFFu, s1, 2, 4);
        s1 += __shfl_down_sync(0xFFFFFFFFu, s1, 1, 4);
        if (tig == 0) {
            red[(wm * 64 + mi * 16 + g) * 4 + wn]     = s0;
            red[(wm * 64 + mi * 16 + 8 + g) * 4 + wn] = s1;
        }
    }
    __syncthreads();
    if (tid < 128) {
        float v = red[tid * 4] + red[tid * 4 + 1] + red[tid * 4 + 2] + red[tid * 4 + 3];
        g_part[(size_t)blockIdx.x * MM + m0 + tid] = v;
    }
}

// ---------------------------------------------------------------------------
// softmax over full sequence, then mask + renormalize.
// ---------------------------------------------------------------------------
__global__ __launch_bounds__(256) void softmax_kernel(const int* __restrict__ seqlen)
{
    __shared__ float sc[SS];
    __shared__ float red[256];
    __shared__ float red2[256];

    const int b = blockIdx.x, tid = threadIdx.x;
    const int len = seqlen[b];

    for (int s = tid; s < SS; s += 256) {
        float v = 0.f;
        #pragma unroll
        for (int j = 0; j < NT; j++)
            v += g_part[(size_t)j * MM + (size_t)b * SS + s];
        sc[s] = v;
    }
    __syncthreads();

    float m = -INFINITY;
    for (int s = tid; s < SS; s += 256) m = fmaxf(m, sc[s]);
    red[tid] = m;
    __syncthreads();
    for (int o = 128; o > 0; o >>= 1) {
        if (tid < o) red[tid] = fmaxf(red[tid], red[tid + o]);
        __syncthreads();
    }
    m = red[0];
    __syncthreads();

    float z = 0.f, zm = 0.f;
    for (int s = tid; s < SS; s += 256) {
        float e = expf(sc[s] - m);
        z += e;
        if (s < len) zm += e;
    }
    red[tid] = z; red2[tid] = zm;
    __syncthreads();
    for (int o = 128; o > 0; o >>= 1) {
        if (tid < o) { red[tid] += red[tid + o]; red2[tid] += red2[tid + o]; }
        __syncthreads();
    }
    z = red[0]; zm = red2[0];

    const float inv = 1.f / (zm + 1e-6f * z);
    for (int s = tid; s < SS; s += 256) {
        float e = (s < len) ? expf(sc[s] - m) * inv : 0.f;
        g_attn[(size_t)b * SS + s] = e;
    }
}

// ---------------------------------------------------------------------------
// pooling partials + reduce
// ---------------------------------------------------------------------------
__global__ __launch_bounds__(HH) void pool_kernel(
    const float* __restrict__ X, const int* __restrict__ seqlen)
{
    const int b = blockIdx.x, c = blockIdx.y, h = threadIdx.x;
    const int s0 = c * SCHUNK;
    const int len = seqlen[b];

    __shared__ float at[SCHUNK];
    if (h < SCHUNK) at[h] = g_attn[(size_t)b * SS + s0 + h];
    __syncthreads();

    float acc = 0.f;
    int end = len - s0;
    if (end > SCHUNK) end = SCHUNK;
    if (end > 0) {
        const float* xp = &X[((size_t)b * SS + s0) * HH + h];
        #pragma unroll 8
        for (int s = 0; s < end; s++)
            acc = fmaf(xp[(size_t)s * HH], at[s], acc);
    }
    g_pout[((size_t)b * NCHUNK + c) * HH + h] = acc;
}

__global__ __launch_bounds__(256) void reduce_out_kernel(float* __restrict__ out)
{
    int i = blockIdx.x * blockDim.x + threadIdx.x;
    if (i >= BB * HH) return;
    int b = i / HH, h = i % HH;
    float v = 0.f;
    #pragma unroll
    for (int c = 0; c < NCHUNK; c++)
        v += g_pout[((size_t)b * NCHUNK + c) * HH + h];
    out[i] = v;
}

// ---------------------------------------------------------------------------
extern "C" void kernel_launch(void* const* d_in, const int* in_sizes, int n_in,
                              void* d_out, int out_size)
{
    const float* X      = (const float*)d_in[0];
    const int*   seqlen = (const int*)  d_in[1];
    const float* W      = (const float*)d_in[2];
    const float* bias   = (const float*)d_in[3];
    const float* wat    = (const float*)d_in[4];
    float*       out    = (float*)d_out;

    cudaFuncSetAttribute(gemm_score_mma,
                         cudaFuncAttributeMaxDynamicSharedMemorySize, SMTOTAL);

    prep_w<<<dim3(16, 16), dim3(32, 8)>>>(W);

    dim3 ggemm(NT, MM / BM);                 // (4, 1024)
    gemm_score_mma<<<ggemm, 256, SMTOTAL>>>(X, bias, wat);

    softmax_kernel<<<BB, 256>>>(seqlen);

    dim3 gpool(BB, NCHUNK);
    pool_kernel<<<gpool, HH>>>(X, seqlen);

    reduce_out_kernel<<<(BB * HH + 255) / 256, 256>>>(out);
}

// round 4
// speedup vs baseline: 1.9007x; 1.0912x over previous
#include <cuda_runtime.h>
#include <cuda_bf16.h>
#include <math.h>
#include <stdint.h>

// ---------------- problem constants ----------------
#define BB 64
#define SS 2048
#define HH 512
#define MM (BB * SS)            // 131072 rows
#define BM 128
#define BN 128
#define BK 64
#define NKC (HH / BK)           // 8 k-chunks
#define NT  (HH / BN)           // 4 n-tiles

#define SCHUNK 128
#define NCHUNK (SS / SCHUNK)    // 16

// SMEM layout (bytes). Rows padded to 144 B -> conflict-free ldmatrix phases.
#define RS    144
#define AHI   0
#define ALO   (128 * RS)        // 18432
#define BHI   (2 * 128 * RS)    // 36864
#define BLO   (3 * 128 * RS)    // 55296
#define STAGE (4 * 128 * RS)    // 73728
#define REDOFF (2 * STAGE)      // 147456
#define SMTOTAL (REDOFF + 128 * 4 * 4)   // 149504

// ---------------- scratch (static device mem) ----------------
__device__ float g_part[NT * MM];
__device__ float g_attn[MM];
__device__ float g_pout[BB * NCHUNK * HH];
__device__ __nv_bfloat16 g_Whi[HH * HH];   // Wt[n,k] = W[k,n], hi split
__device__ __nv_bfloat16 g_Wlo[HH * HH];   // lo split

// ---------------- helpers ----------------
__device__ __forceinline__ uint32_t smem_u32(const void* p) {
    uint32_t a;
    asm("{ .reg .u64 t; cvta.to.shared.u64 t, %1; cvt.u32.u64 %0, t; }"
        : "=r"(a) : "l"(p));
    return a;
}
__device__ __forceinline__ void cpa16(uint32_t dst, const void* src) {
    asm volatile("cp.async.cg.shared.global [%0], [%1], 16;"
                 :: "r"(dst), "l"(src) : "memory");
}
__device__ __forceinline__ void mma_bf16(float* d, const uint32_t* a, const uint32_t* b) {
    asm volatile("mma.sync.aligned.m16n8k16.row.col.f32.bf16.bf16.f32 "
                 "{%0,%1,%2,%3}, {%4,%5,%6,%7}, {%8,%9}, {%0,%1,%2,%3};"
                 : "+f"(d[0]), "+f"(d[1]), "+f"(d[2]), "+f"(d[3])
                 : "r"(a[0]), "r"(a[1]), "r"(a[2]), "r"(a[3]),
                   "r"(b[0]), "r"(b[1]));
}
__device__ __forceinline__ void ldsm4(uint32_t& r0, uint32_t& r1, uint32_t& r2,
                                      uint32_t& r3, uint32_t addr) {
    asm volatile("ldmatrix.sync.aligned.m8n8.x4.shared.b16 {%0,%1,%2,%3}, [%4];"
                 : "=r"(r0), "=r"(r1), "=r"(r2), "=r"(r3) : "r"(addr));
}
__device__ __forceinline__ uint32_t pack_bf2(__nv_bfloat16 x, __nv_bfloat16 y) {
    return (uint32_t)__bfloat16_as_ushort(x)
         | ((uint32_t)__bfloat16_as_ushort(y) << 16);
}

// ---------------------------------------------------------------------------
// W prep: transpose + bf16 hi/lo split.  Wt[n,k] = W[k,n]
// ---------------------------------------------------------------------------
__global__ void prep_w(const float* __restrict__ W) {
    __shared__ float t[32][33];
    int n0 = blockIdx.x * 32, k0 = blockIdx.y * 32;
    int tx = threadIdx.x, ty = threadIdx.y;      // 32 x 8
    #pragma unroll
    for (int r = 0; r < 32; r += 8)
        t[ty + r][tx] = W[(size_t)(k0 + ty + r) * HH + n0 + tx];
    __syncthreads();
    #pragma unroll
    for (int r = 0; r < 32; r += 8) {
        int n = n0 + ty + r, k = k0 + tx;
        float x = t[tx][ty + r];
        __nv_bfloat16 h = __float2bfloat16_rn(x);
        g_Whi[(size_t)n * HH + k] = h;
        g_Wlo[(size_t)n * HH + k] = __float2bfloat16_rn(x - __bfloat162float(h));
    }
}

// ---------------------------------------------------------------------------
// Split-bf16 HMMA GEMM (ldmatrix operand path) + fused tanh-dot epilogue.
// grid (NT, MM/BM), 256 threads (8 warps, 2M x 4N, warp tile 64x32), BK=64.
// ---------------------------------------------------------------------------
__global__ __launch_bounds__(256, 1) void gemm_score_mma(
    const float* __restrict__ A, const float* __restrict__ bias,
    const float* __restrict__ wat)
{
    extern __shared__ char sm[];
    const uint32_t sbase = smem_u32(sm);
    const int tid = threadIdx.x, lane = tid & 31, wid = tid >> 5;
    const int g = lane >> 2, tig = lane & 3;
    const int wm = wid >> 2, wn = wid & 3;
    const int m0 = blockIdx.y * BM, n0 = blockIdx.x * BN;

    const int arow = tid >> 1;            // 0..127
    const int af   = (tid & 1) * 8;       // float4 index base (0 or 8)

    // ldmatrix lane-address offsets (within a stage)
    // B tile pair: t = lane>>3; n_off = (t>>1)*8; k_off = (t&1)*8
    const uint32_t boff = (uint32_t)((wn * 32 + ((lane >> 4) * 8) + (lane & 7)) * RS
                                     + (((lane >> 3) & 1) * 8) * 2);
    // A tile: t = lane>>3; m_off = (t&1)*8; k_off = (t>>1)*8
    const uint32_t aoff = (uint32_t)((wm * 64 + (((lane >> 3) & 1) * 8) + (lane & 7)) * RS
                                     + ((lane >> 4) * 8) * 2);

    float acc[4][4][4] = {};
    float4 rA[8];

    // ---- prologue: chunk 0 ----
    {
        const float* p = &A[(size_t)(m0 + arow) * HH + af * 4];
        #pragma unroll
        for (int q = 0; q < 8; q++) rA[q] = *(const float4*)(p + q * 4);
        #pragma unroll
        for (int t = 0; t < 8; t++) {
            int i = tid + t * 256;
            int hl = i >> 10, r = (i >> 3) & 127, seg = i & 7;
            const __nv_bfloat16* src =
                (hl ? g_Wlo : g_Whi) + (size_t)(n0 + r) * HH + seg * 8;
            cpa16(sbase + (hl ? BLO : BHI) + r * RS + seg * 16, src);
        }
        asm volatile("cp.async.commit_group;" ::: "memory");
        #pragma unroll
        for (int q = 0; q < 8; q++) {
            float4 v = rA[q];
            __nv_bfloat16 h0 = __float2bfloat16_rn(v.x), h1 = __float2bfloat16_rn(v.y);
            __nv_bfloat16 h2 = __float2bfloat16_rn(v.z), h3 = __float2bfloat16_rn(v.w);
            uint2 hp = make_uint2(pack_bf2(h0, h1), pack_bf2(h2, h3));
            uint2 lp = make_uint2(
                pack_bf2(__float2bfloat16_rn(v.x - __bfloat162float(h0)),
                         __float2bfloat16_rn(v.y - __bfloat162float(h1))),
                pack_bf2(__float2bfloat16_rn(v.z - __bfloat162float(h2)),
                         __float2bfloat16_rn(v.w - __bfloat162float(h3))));
            int off = arow * RS + (af + q) * 8;
            *(uint2*)(sm + AHI + off) = hp;
            *(uint2*)(sm + ALO + off) = lp;
        }
        asm volatile("cp.async.wait_group 0;" ::: "memory");
        __syncthreads();
    }

    for (int c = 0; c < NKC; c++) {
        const int pb = c & 1, nb = pb ^ 1;
        if (c + 1 < NKC) {
            const float* p = &A[(size_t)(m0 + arow) * HH + (c + 1) * BK + af * 4];
            #pragma unroll
            for (int q = 0; q < 8; q++) rA[q] = *(const float4*)(p + q * 4);
            #pragma unroll
            for (int t = 0; t < 8; t++) {
                int i = tid + t * 256;
                int hl = i >> 10, r = (i >> 3) & 127, seg = i & 7;
                const __nv_bfloat16* src =
                    (hl ? g_Wlo : g_Whi) + (size_t)(n0 + r) * HH + (c + 1) * BK + seg * 8;
                cpa16(sbase + nb * STAGE + (hl ? BLO : BHI) + r * RS + seg * 16, src);
            }
            asm volatile("cp.async.commit_group;" ::: "memory");
        }

        // ---- compute on buffer pb ----
        {
            const uint32_t st = sbase + pb * STAGE;
            #pragma unroll
            for (int ks = 0; ks < 4; ks++) {
                const uint32_t kso = (uint32_t)(ks * 32);
                uint32_t bh[4][2], bl[4][2];
                ldsm4(bh[0][0], bh[0][1], bh[1][0], bh[1][1], st + BHI + boff + kso);
                ldsm4(bh[2][0], bh[2][1], bh[3][0], bh[3][1], st + BHI + boff + kso + 16 * RS);
                ldsm4(bl[0][0], bl[0][1], bl[1][0], bl[1][1], st + BLO + boff + kso);
                ldsm4(bl[2][0], bl[2][1], bl[3][0], bl[3][1], st + BLO + boff + kso + 16 * RS);
                #pragma unroll
                for (int mi = 0; mi < 4; mi++) {
                    uint32_t ah[4], al[4];
                    const uint32_t am = aoff + (uint32_t)(mi * 16 * RS) + kso;
                    ldsm4(ah[0], ah[1], ah[2], ah[3], st + AHI + am);
                    ldsm4(al[0], al[1], al[2], al[3], st + ALO + am);
                    #pragma unroll
                    for (int ni = 0; ni < 4; ni++) {
                        mma_bf16(acc[mi][ni], ah, bh[ni]);
                        mma_bf16(acc[mi][ni], ah, bl[ni]);
                        mma_bf16(acc[mi][ni], al, bh[ni]);
                    }
                }
            }
        }

        if (c + 1 < NKC) {
            #pragma unroll
            for (int q = 0; q < 8; q++) {
                float4 v = rA[q];
                __nv_bfloat16 h0 = __float2bfloat16_rn(v.x), h1 = __float2bfloat16_rn(v.y);
                __nv_bfloat16 h2 = __float2bfloat16_rn(v.z), h3 = __float2bfloat16_rn(v.w);
                uint2 hp = make_uint2(pack_bf2(h0, h1), pack_bf2(h2, h3));
                uint2 lp = make_uint2(
                    pack_bf2(__float2bfloat16_rn(v.x - __bfloat162float(h0)),
                             __float2bfloat16_rn(v.y - __bfloat162float(h1))),
                    pack_bf2(__float2bfloat16_rn(v.z - __bfloat162float(h2)),
                             __float2bfloat16_rn(v.w - __bfloat162float(h3))));
                int off = arow * RS + (af + q) * 8;
                *(uint2*)(sm + nb * STAGE + AHI + off) = hp;
                *(uint2*)(sm + nb * STAGE + ALO + off) = lp;
            }
            asm volatile("cp.async.wait_group 0;" ::: "memory");
            __syncthreads();
        }
    }

    // ---- epilogue: tanh(z + b) * w, reduced over this CTA's 128 columns ----
    float* red = (float*)(sm + REDOFF);
    #pragma unroll
    for (int mi = 0; mi < 4; mi++) {
        float s0 = 0.f, s1 = 0.f;
        #pragma unroll
        for (int ni = 0; ni < 4; ni++) {
            int col = n0 + wn * 32 + ni * 8 + tig * 2;
            float2 bb = *(const float2*)&bias[col];
            float2 ww = *(const float2*)&wat[col];
            s0 += tanhf(acc[mi][ni][0] + bb.x) * ww.x
                + tanhf(acc[mi][ni][1] + bb.y) * ww.y;
            s1 += tanhf(acc[mi][ni][2] + bb.x) * ww.x
                + tanhf(acc[mi][ni][3] + bb.y) * ww.y;
        }
        s0 += __shfl_down_sync(0xFFFFFFFFu, s0, 2, 4);
        s0 += __shfl_down_sync(0xFFFFFFFFu, s0, 1, 4);
        s1 += __shfl_down_sync(0xFFFFFFFFu, s1, 2, 4);
        s1 += __shfl_down_sync(0xFFFFFFFFu, s1, 1, 4);
        if (tig == 0) {
            red[(wm * 64 + mi * 16 + g) * 4 + wn]     = s0;
            red[(wm * 64 + mi * 16 + 8 + g) * 4 + wn] = s1;
        }
    }
    __syncthreads();
    if (tid < 128) {
        float v = red[tid * 4] + red[tid * 4 + 1] + red[tid * 4 + 2] + red[tid * 4 + 3];
        g_part[(size_t)blockIdx.x * MM + m0 + tid] = v;
    }
}

// ---------------------------------------------------------------------------
// softmax over full sequence, then mask + renormalize.
// ---------------------------------------------------------------------------
__global__ __launch_bounds__(256) void softmax_kernel(const int* __restrict__ seqlen)
{
    __shared__ float sc[SS];
    __shared__ float red[256];
    __shared__ float red2[256];

    const int b = blockIdx.x, tid = threadIdx.x;
    const int len = seqlen[b];

    for (int s = tid; s < SS; s += 256) {
        float v = 0.f;
        #pragma unroll
        for (int j = 0; j < NT; j++)
            v += g_part[(size_t)j * MM + (size_t)b * SS + s];
        sc[s] = v;
    }
    __syncthreads();

    float m = -INFINITY;
    for (int s = tid; s < SS; s += 256) m = fmaxf(m, sc[s]);
    red[tid] = m;
    __syncthreads();
    for (int o = 128; o > 0; o >>= 1) {
        if (tid < o) red[tid] = fmaxf(red[tid], red[tid + o]);
        __syncthreads();
    }
    m = red[0];
    __syncthreads();

    float z = 0.f, zm = 0.f;
    for (int s = tid; s < SS; s += 256) {
        float e = expf(sc[s] - m);
        z += e;
        if (s < len) zm += e;
    }
    red[tid] = z; red2[tid] = zm;
    __syncthreads();
    for (int o = 128; o > 0; o >>= 1) {
        if (tid < o) { red[tid] += red[tid + o]; red2[tid] += red2[tid + o]; }
        __syncthreads();
    }
    z = red[0]; zm = red2[0];

    const float inv = 1.f / (zm + 1e-6f * z);
    for (int s = tid; s < SS; s += 256) {
        float e = (s < len) ? expf(sc[s] - m) * inv : 0.f;
        g_attn[(size_t)b * SS + s] = e;
    }
}

// ---------------------------------------------------------------------------
// pooling partials (4 independent accumulators -> MLP) + reduce
// ---------------------------------------------------------------------------
__global__ __launch_bounds__(HH) void pool_kernel(
    const float* __restrict__ X, const int* __restrict__ seqlen)
{
    const int b = blockIdx.x, c = blockIdx.y, h = threadIdx.x;
    const int s0 = c * SCHUNK;
    const int len = seqlen[b];

    __shared__ float at[SCHUNK];
    if (h < SCHUNK) at[h] = g_attn[(size_t)b * SS + s0 + h];
    __syncthreads();

    int end = len - s0;
    if (end > SCHUNK) end = SCHUNK;
    float a0 = 0.f, a1 = 0.f, a2 = 0.f, a3 = 0.f;
    if (end > 0) {
        const float* xp = &X[((size_t)b * SS + s0) * HH + h];
        int s = 0;
        for (; s + 3 < end; s += 4) {
            a0 = fmaf(xp[(size_t)(s + 0) * HH], at[s + 0], a0);
            a1 = fmaf(xp[(size_t)(s + 1) * HH], at[s + 1], a1);
            a2 = fmaf(xp[(size_t)(s + 2) * HH], at[s + 2], a2);
            a3 = fmaf(xp[(size_t)(s + 3) * HH], at[s + 3], a3);
        }
        for (; s < end; s++)
            a0 = fmaf(xp[(size_t)s * HH], at[s], a0);
    }
    g_pout[((size_t)b * NCHUNK + c) * HH + h] = (a0 + a1) + (a2 + a3);
}

__global__ __launch_bounds__(256) void reduce_out_kernel(float* __restrict__ out)
{
    int i = blockIdx.x * blockDim.x + threadIdx.x;
    if (i >= BB * HH) return;
    int b = i / HH, h = i % HH;
    float v = 0.f;
    #pragma unroll
    for (int c = 0; c < NCHUNK; c++)
        v += g_pout[((size_t)b * NCHUNK + c) * HH + h];
    out[i] = v;
}

// ---------------------------------------------------------------------------
extern "C" void kernel_launch(void* const* d_in, const int* in_sizes, int n_in,
                              void* d_out, int out_size)
{
    const float* X      = (const float*)d_in[0];
    const int*   seqlen = (const int*)  d_in[1];
    const float* W      = (const float*)d_in[2];
    const float* bias   = (const float*)d_in[3];
    const float* wat    = (const float*)d_in[4];
    float*       out    = (float*)d_out;

    cudaFuncSetAttribute(gemm_score_mma,
                         cudaFuncAttributeMaxDynamicSharedMemorySize, SMTOTAL);

    prep_w<<<dim3(16, 16), dim3(32, 8)>>>(W);

    dim3 ggemm(NT, MM / BM);                 // (4, 1024)
    gemm_score_mma<<<ggemm, 256, SMTOTAL>>>(X, bias, wat);

    softmax_kernel<<<BB, 256>>>(seqlen);

    dim3 gpool(BB, NCHUNK);                  // (64, 16)
    pool_kernel<<<gpool, HH>>>(X, seqlen);

    reduce_out_kernel<<<(BB * HH + 255) / 256, 256>>>(out);
}

// round 5
// speedup vs baseline: 2.4351x; 1.2812x over previous
#include <cuda_runtime.h>
#include <cuda_fp16.h>
#include <math.h>
#include <stdint.h>

// ---------------- problem constants ----------------
#define BB 64
#define SS 2048
#define HH 512
#define MM (BB * SS)            // 131072 rows
#define BM 128
#define BN 128
#define BK 64
#define NKC (HH / BK)           // 8 k-chunks
#define NT  (HH / BN)           // 4 n-tiles

#define SCHUNK 128
#define NCHUNK (SS / SCHUNK)    // 16

// SMEM layout (bytes). Rows padded to 144 B -> conflict-free ldmatrix phases.
#define RS    144
#define AHI   0
#define BHI   (128 * RS)        // 18432
#define BLO   (2 * 128 * RS)    // 36864
#define STAGE (3 * 128 * RS)    // 55296
#define REDOFF (2 * STAGE)      // 110592
#define SMTOTAL (REDOFF + 128 * 4 * 4)   // 112640

// ---------------- scratch (static device mem) ----------------
__device__ float g_part[NT * MM];
__device__ float g_attn[MM];
__device__ float g_pout[BB * NCHUNK * HH];
__device__ __half g_Whi[HH * HH];   // Wt[n,k] = W[k,n], fp16 hi split
__device__ __half g_Wlo[HH * HH];   // fp16 lo split (residual)

// ---------------- helpers ----------------
__device__ __forceinline__ uint32_t smem_u32(const void* p) {
    uint32_t a;
    asm("{ .reg .u64 t; cvta.to.shared.u64 t, %1; cvt.u32.u64 %0, t; }"
        : "=r"(a) : "l"(p));
    return a;
}
__device__ __forceinline__ void cpa16(uint32_t dst, const void* src) {
    asm volatile("cp.async.cg.shared.global [%0], [%1], 16;"
                 :: "r"(dst), "l"(src) : "memory");
}
__device__ __forceinline__ void mma_f16(float* d, const uint32_t* a, const uint32_t* b) {
    asm volatile("mma.sync.aligned.m16n8k16.row.col.f32.f16.f16.f32 "
                 "{%0,%1,%2,%3}, {%4,%5,%6,%7}, {%8,%9}, {%0,%1,%2,%3};"
                 : "+f"(d[0]), "+f"(d[1]), "+f"(d[2]), "+f"(d[3])
                 : "r"(a[0]), "r"(a[1]), "r"(a[2]), "r"(a[3]),
                   "r"(b[0]), "r"(b[1]));
}
__device__ __forceinline__ void ldsm4(uint32_t& r0, uint32_t& r1, uint32_t& r2,
                                      uint32_t& r3, uint32_t addr) {
    asm volatile("ldmatrix.sync.aligned.m8n8.x4.shared.b16 {%0,%1,%2,%3}, [%4];"
                 : "=r"(r0), "=r"(r1), "=r"(r2), "=r"(r3) : "r"(addr));
}
__device__ __forceinline__ uint32_t pack_h2(float x, float y) {
    __half2 h = __floats2half2_rn(x, y);
    return *(uint32_t*)&h;
}

// ---------------------------------------------------------------------------
// W prep: transpose + fp16 hi/lo split.  Wt[n,k] = W[k,n]
// ---------------------------------------------------------------------------
__global__ void prep_w(const float* __restrict__ W) {
    __shared__ float t[32][33];
    int n0 = blockIdx.x * 32, k0 = blockIdx.y * 32;
    int tx = threadIdx.x, ty = threadIdx.y;      // 32 x 8
    #pragma unroll
    for (int r = 0; r < 32; r += 8)
        t[ty + r][tx] = W[(size_t)(k0 + ty + r) * HH + n0 + tx];
    __syncthreads();
    #pragma unroll
    for (int r = 0; r < 32; r += 8) {
        int n = n0 + ty + r, k = k0 + tx;
        float x = t[tx][ty + r];
        __half h = __float2half_rn(x);
        g_Whi[(size_t)n * HH + k] = h;
        g_Wlo[(size_t)n * HH + k] = __float2half_rn(x - __half2float(h));
    }
}

// ---------------------------------------------------------------------------
// 2-term fp16 HMMA GEMM (ldmatrix operands) + fused tanh-dot epilogue.
// grid (NT, MM/BM), 256 threads (8 warps, 2M x 4N, warp tile 64x32), BK=64.
//   z = Ah * (Whi + Wlo)   (exactly X(fp16) * W; only X residual dropped)
// ---------------------------------------------------------------------------
__global__ __launch_bounds__(256, 1) void gemm_score_mma(
    const float* __restrict__ A, const float* __restrict__ bias,
    const float* __restrict__ wat)
{
    extern __shared__ char sm[];
    const uint32_t sbase = smem_u32(sm);
    const int tid = threadIdx.x, lane = tid & 31, wid = tid >> 5;
    const int g = lane >> 2, tig = lane & 3;
    const int wm = wid >> 2, wn = wid & 3;
    const int m0 = blockIdx.y * BM, n0 = blockIdx.x * BN;

    const int arow = tid >> 1;            // 0..127
    const int af   = (tid & 1) * 8;       // float4 index base (0 or 8)

    // ldmatrix lane-address offsets (within a stage)
    const uint32_t boff = (uint32_t)((wn * 32 + ((lane >> 4) * 8) + (lane & 7)) * RS
                                     + (((lane >> 3) & 1) * 8) * 2);
    const uint32_t aoff = (uint32_t)((wm * 64 + (((lane >> 3) & 1) * 8) + (lane & 7)) * RS
                                     + ((lane >> 4) * 8) * 2);

    float acc[4][4][4] = {};
    float4 rA[8];

    // ---- prologue: chunk 0 ----
    {
        const float* p = &A[(size_t)(m0 + arow) * HH + af * 4];
        #pragma unroll
        for (int q = 0; q < 8; q++) rA[q] = *(const float4*)(p + q * 4);
        #pragma unroll
        for (int t = 0; t < 8; t++) {
            int i = tid + t * 256;
            int hl = i >> 10, r = (i >> 3) & 127, seg = i & 7;
            const __half* src =
                (hl ? g_Wlo : g_Whi) + (size_t)(n0 + r) * HH + seg * 8;
            cpa16(sbase + (hl ? BLO : BHI) + r * RS + seg * 16, src);
        }
        asm volatile("cp.async.commit_group;" ::: "memory");
        #pragma unroll
        for (int q = 0; q < 8; q++) {
            float4 v = rA[q];
            uint2 hp = make_uint2(pack_h2(v.x, v.y), pack_h2(v.z, v.w));
            *(uint2*)(sm + AHI + arow * RS + (af + q) * 8) = hp;
        }
        asm volatile("cp.async.wait_group 0;" ::: "memory");
        __syncthreads();
    }

    for (int c = 0; c < NKC; c++) {
        const int pb = c & 1, nb = pb ^ 1;
        if (c + 1 < NKC) {
            const float* p = &A[(size_t)(m0 + arow) * HH + (c + 1) * BK + af * 4];
            #pragma unroll
            for (int q = 0; q < 8; q++) rA[q] = *(const float4*)(p + q * 4);
            #pragma unroll
            for (int t = 0; t < 8; t++) {
                int i = tid + t * 256;
                int hl = i >> 10, r = (i >> 3) & 127, seg = i & 7;
                const __half* src =
                    (hl ? g_Wlo : g_Whi) + (size_t)(n0 + r) * HH + (c + 1) * BK + seg * 8;
                cpa16(sbase + nb * STAGE + (hl ? BLO : BHI) + r * RS + seg * 16, src);
            }
            asm volatile("cp.async.commit_group;" ::: "memory");
        }

        // ---- compute on buffer pb ----
        {
            const uint32_t st = sbase + pb * STAGE;
            #pragma unroll
            for (int ks = 0; ks < 4; ks++) {
                const uint32_t kso = (uint32_t)(ks * 32);
                uint32_t bh[4][2], bl[4][2];
                ldsm4(bh[0][0], bh[0][1], bh[1][0], bh[1][1], st + BHI + boff + kso);
                ldsm4(bh[2][0], bh[2][1], bh[3][0], bh[3][1], st + BHI + boff + kso + 16 * RS);
                ldsm4(bl[0][0], bl[0][1], bl[1][0], bl[1][1], st + BLO + boff + kso);
                ldsm4(bl[2][0], bl[2][1], bl[3][0], bl[3][1], st + BLO + boff + kso + 16 * RS);
                #pragma unroll
                for (int mi = 0; mi < 4; mi++) {
                    uint32_t ah[4];
                    const uint32_t am = aoff + (uint32_t)(mi * 16 * RS) + kso;
                    ldsm4(ah[0], ah[1], ah[2], ah[3], st + AHI + am);
                    #pragma unroll
                    for (int ni = 0; ni < 4; ni++) {
                        mma_f16(acc[mi][ni], ah, bh[ni]);
                        mma_f16(acc[mi][ni], ah, bl[ni]);
                    }
                }
            }
        }

        if (c + 1 < NKC) {
            #pragma unroll
            for (int q = 0; q < 8; q++) {
                float4 v = rA[q];
                uint2 hp = make_uint2(pack_h2(v.x, v.y), pack_h2(v.z, v.w));
                *(uint2*)(sm + nb * STAGE + AHI + arow * RS + (af + q) * 8) = hp;
            }
            asm volatile("cp.async.wait_group 0;" ::: "memory");
            __syncthreads();
        }
    }

    // ---- epilogue: tanh(z + b) * w, reduced over this CTA's 128 columns ----
    float* red = (float*)(sm + REDOFF);
    #pragma unroll
    for (int mi = 0; mi < 4; mi++) {
        float s0 = 0.f, s1 = 0.f;
        #pragma unroll
        for (int ni = 0; ni < 4; ni++) {
            int col = n0 + wn * 32 + ni * 8 + tig * 2;
            float2 bb = *(const float2*)&bias[col];
            float2 ww = *(const float2*)&wat[col];
            s0 += tanhf(acc[mi][ni][0] + bb.x) * ww.x
                + tanhf(acc[mi][ni][1] + bb.y) * ww.y;
            s1 += tanhf(acc[mi][ni][2] + bb.x) * ww.x
                + tanhf(acc[mi][ni][3] + bb.y) * ww.y;
        }
        s0 += __shfl_down_sync(0xFFFFFFFFu, s0, 2, 4);
        s0 += __shfl_down_sync(0xFFFFFFFFu, s0, 1, 4);
        s1 += __shfl_down_sync(0xFFFFFFFFu, s1, 2, 4);
        s1 += __shfl_down_sync(0xFFFFFFFFu, s1, 1, 4);
        if (tig == 0) {
            red[(wm * 64 + mi * 16 + g) * 4 + wn]     = s0;
            red[(wm * 64 + mi * 16 + 8 + g) * 4 + wn] = s1;
        }
    }
    __syncthreads();
    if (tid < 128) {
        float v = red[tid * 4] + red[tid * 4 + 1] + red[tid * 4 + 2] + red[tid * 4 + 3];
        g_part[(size_t)blockIdx.x * MM + m0 + tid] = v;
    }
}

// ---------------------------------------------------------------------------
// softmax over full sequence, then mask + renormalize.
// ---------------------------------------------------------------------------
__global__ __launch_bounds__(256) void softmax_kernel(const int* __restrict__ seqlen)
{
    __shared__ float sc[SS];
    __shared__ float red[256];
    __shared__ float red2[256];

    const int b = blockIdx.x, tid = threadIdx.x;
    const int len = seqlen[b];

    for (int s = tid; s < SS; s += 256) {
        float v = 0.f;
        #pragma unroll
        for (int j = 0; j < NT; j++)
            v += g_part[(size_t)j * MM + (size_t)b * SS + s];
        sc[s] = v;
    }
    __syncthreads();

    float m = -INFINITY;
    for (int s = tid; s < SS; s += 256) m = fmaxf(m, sc[s]);
    red[tid] = m;
    __syncthreads();
    for (int o = 128; o > 0; o >>= 1) {
        if (tid < o) red[tid] = fmaxf(red[tid], red[tid + o]);
        __syncthreads();
    }
    m = red[0];
    __syncthreads();

    float z = 0.f, zm = 0.f;
    for (int s = tid; s < SS; s += 256) {
        float e = expf(sc[s] - m);
        z += e;
        if (s < len) zm += e;
    }
    red[tid] = z; red2[tid] = zm;
    __syncthreads();
    for (int o = 128; o > 0; o >>= 1) {
        if (tid < o) { red[tid] += red[tid + o]; red2[tid] += red2[tid + o]; }
        __syncthreads();
    }
    z = red[0]; zm = red2[0];

    const float inv = 1.f / (zm + 1e-6f * z);
    for (int s = tid; s < SS; s += 256) {
        float e = (s < len) ? expf(sc[s] - m) * inv : 0.f;
        g_attn[(size_t)b * SS + s] = e;
    }
}

// ---------------------------------------------------------------------------
// pooling partials (4 independent accumulators) + reduce
// ---------------------------------------------------------------------------
__global__ __launch_bounds__(HH) void pool_kernel(
    const float* __restrict__ X, const int* __restrict__ seqlen)
{
    const int b = blockIdx.x, c = blockIdx.y, h = threadIdx.x;
    const int s0 = c * SCHUNK;
    const int len = seqlen[b];

    __shared__ float at[SCHUNK];
    if (h < SCHUNK) at[h] = g_attn[(size_t)b * SS + s0 + h];
    __syncthreads();

    int end = len - s0;
    if (end > SCHUNK) end = SCHUNK;
    float a0 = 0.f, a1 = 0.f, a2 = 0.f, a3 = 0.f;
    if (end > 0) {
        const float* xp = &X[((size_t)b * SS + s0) * HH + h];
        int s = 0;
        for (; s + 3 < end; s += 4) {
            a0 = fmaf(xp[(size_t)(s + 0) * HH], at[s + 0], a0);
            a1 = fmaf(xp[(size_t)(s + 1) * HH], at[s + 1], a1);
            a2 = fmaf(xp[(size_t)(s + 2) * HH], at[s + 2], a2);
            a3 = fmaf(xp[(size_t)(s + 3) * HH], at[s + 3], a3);
        }
        for (; s < end; s++)
            a0 = fmaf(xp[(size_t)s * HH], at[s], a0);
    }
    g_pout[((size_t)b * NCHUNK + c) * HH + h] = (a0 + a1) + (a2 + a3);
}

__global__ __launch_bounds__(256) void reduce_out_kernel(float* __restrict__ out)
{
    int i = blockIdx.x * blockDim.x + threadIdx.x;
    if (i >= BB * HH) return;
    int b = i / HH, h = i % HH;
    float v = 0.f;
    #pragma unroll
    for (int c = 0; c < NCHUNK; c++)
        v += g_pout[((size_t)b * NCHUNK + c) * HH + h];
    out[i] = v;
}

// ---------------------------------------------------------------------------
extern "C" void kernel_launch(void* const* d_in, const int* in_sizes, int n_in,
                              void* d_out, int out_size)
{
    const float* X      = (const float*)d_in[0];
    const int*   seqlen = (const int*)  d_in[1];
    const float* W      = (const float*)d_in[2];
    const float* bias   = (const float*)d_in[3];
    const float* wat    = (const float*)d_in[4];
    float*       out    = (float*)d_out;

    cudaFuncSetAttribute(gemm_score_mma,
                         cudaFuncAttributeMaxDynamicSharedMemorySize, SMTOTAL);

    prep_w<<<dim3(16, 16), dim3(32, 8)>>>(W);

    dim3 ggemm(NT, MM / BM);                 // (4, 1024)
    gemm_score_mma<<<ggemm, 256, SMTOTAL>>>(X, bias, wat);

    softmax_kernel<<<BB, 256>>>(seqlen);

    dim3 gpool(BB, NCHUNK);                  // (64, 16)
    pool_kernel<<<gpool, HH>>>(X, seqlen);

    reduce_out_kernel<<<(BB * HH + 255) / 256, 256>>>(out);
}

// round 6
// speedup vs baseline: 2.7214x; 1.1176x over previous
#include <cuda_runtime.h>
#include <cuda_fp16.h>
#include <math.h>
#include <stdint.h>

// ---------------- problem constants ----------------
#define BB 64
#define SS 2048
#define HH 512
#define MM (BB * SS)            // 131072 rows
#define BM 128
#define BN 128
#define BK 64
#define NKC (HH / BK)           // 8 k-chunks
#define NT  (HH / BN)           // 4 n-tiles

#define SCHUNK 128
#define NCHUNK (SS / SCHUNK)    // 16

// SMEM layout (bytes). Rows padded to 144 B -> conflict-free ldmatrix phases.
#define RS    144
#define AHI   0
#define BHI   (128 * RS)        // 18432
#define STAGE (2 * 128 * RS)    // 36864
#define REDOFF (2 * STAGE)      // 73728
#define SMTOTAL (REDOFF + 128 * 4 * 4)   // 75776

// ---------------- scratch (static device mem) ----------------
__device__ float g_part[NT * MM];
__device__ float g_attn[MM];
__device__ float g_pout[BB * NCHUNK * HH];
__device__ __half g_Wh[HH * HH];   // Wt[n,k] = fp16(W[k,n])

// ---------------- helpers ----------------
__device__ __forceinline__ uint32_t smem_u32(const void* p) {
    uint32_t a;
    asm("{ .reg .u64 t; cvta.to.shared.u64 t, %1; cvt.u32.u64 %0, t; }"
        : "=r"(a) : "l"(p));
    return a;
}
__device__ __forceinline__ void cpa16(uint32_t dst, const void* src) {
    asm volatile("cp.async.cg.shared.global [%0], [%1], 16;"
                 :: "r"(dst), "l"(src) : "memory");
}
__device__ __forceinline__ void mma_f16(float* d, const uint32_t* a, const uint32_t* b) {
    asm volatile("mma.sync.aligned.m16n8k16.row.col.f32.f16.f16.f32 "
                 "{%0,%1,%2,%3}, {%4,%5,%6,%7}, {%8,%9}, {%0,%1,%2,%3};"
                 : "+f"(d[0]), "+f"(d[1]), "+f"(d[2]), "+f"(d[3])
                 : "r"(a[0]), "r"(a[1]), "r"(a[2]), "r"(a[3]),
                   "r"(b[0]), "r"(b[1]));
}
__device__ __forceinline__ void ldsm4(uint32_t& r0, uint32_t& r1, uint32_t& r2,
                                      uint32_t& r3, uint32_t addr) {
    asm volatile("ldmatrix.sync.aligned.m8n8.x4.shared.b16 {%0,%1,%2,%3}, [%4];"
                 : "=r"(r0), "=r"(r1), "=r"(r2), "=r"(r3) : "r"(addr));
}
__device__ __forceinline__ uint32_t pack_h2(float x, float y) {
    __half2 h = __floats2half2_rn(x, y);
    return *(uint32_t*)&h;
}

// ---------------------------------------------------------------------------
// W prep: transpose + fp16 round.  Wt[n,k] = fp16(W[k,n])
// ---------------------------------------------------------------------------
__global__ void prep_w(const float* __restrict__ W) {
    __shared__ float t[32][33];
    int n0 = blockIdx.x * 32, k0 = blockIdx.y * 32;
    int tx = threadIdx.x, ty = threadIdx.y;      // 32 x 8
    #pragma unroll
    for (int r = 0; r < 32; r += 8)
        t[ty + r][tx] = W[(size_t)(k0 + ty + r) * HH + n0 + tx];
    __syncthreads();
    #pragma unroll
    for (int r = 0; r < 32; r += 8) {
        int n = n0 + ty + r, k = k0 + tx;
        g_Wh[(size_t)n * HH + k] = __float2half_rn(t[tx][ty + r]);
    }
}

// ---------------------------------------------------------------------------
// 1-term fp16 HMMA GEMM (ldmatrix operands) + fused tanh-dot epilogue.
// grid (NT, MM/BM), 256 threads (8 warps, 2M x 4N, warp tile 64x32), BK=64.
// ---------------------------------------------------------------------------
__global__ __launch_bounds__(256, 1) void gemm_score_mma(
    const float* __restrict__ A, const float* __restrict__ bias,
    const float* __restrict__ wat)
{
    extern __shared__ char sm[];
    const uint32_t sbase = smem_u32(sm);
    const int tid = threadIdx.x, lane = tid & 31, wid = tid >> 5;
    const int g = lane >> 2, tig = lane & 3;
    const int wm = wid >> 2, wn = wid & 3;
    const int m0 = blockIdx.y * BM, n0 = blockIdx.x * BN;

    const int arow = tid >> 1;            // 0..127
    const int af   = (tid & 1) * 8;       // float4 index base (0 or 8)

    const uint32_t boff = (uint32_t)((wn * 32 + ((lane >> 4) * 8) + (lane & 7)) * RS
                                     + (((lane >> 3) & 1) * 8) * 2);
    const uint32_t aoff = (uint32_t)((wm * 64 + (((lane >> 3) & 1) * 8) + (lane & 7)) * RS
                                     + ((lane >> 4) * 8) * 2);

    float acc[4][4][4] = {};
    float4 rA[8];

    // ---- prologue: chunk 0 ----
    {
        const float* p = &A[(size_t)(m0 + arow) * HH + af * 4];
        #pragma unroll
        for (int q = 0; q < 8; q++) rA[q] = *(const float4*)(p + q * 4);
        #pragma unroll
        for (int t = 0; t < 4; t++) {
            int i = tid + t * 256;
            int r = (i >> 3) & 127, seg = i & 7;
            cpa16(sbase + BHI + r * RS + seg * 16,
                  g_Wh + (size_t)(n0 + r) * HH + seg * 8);
        }
        asm volatile("cp.async.commit_group;" ::: "memory");
        #pragma unroll
        for (int q = 0; q < 8; q++) {
            float4 v = rA[q];
            uint2 hp = make_uint2(pack_h2(v.x, v.y), pack_h2(v.z, v.w));
            *(uint2*)(sm + AHI + arow * RS + (af + q) * 8) = hp;
        }
        asm volatile("cp.async.wait_group 0;" ::: "memory");
        __syncthreads();
    }

    for (int c = 0; c < NKC; c++) {
        const int pb = c & 1, nb = pb ^ 1;
        if (c + 1 < NKC) {
            const float* p = &A[(size_t)(m0 + arow) * HH + (c + 1) * BK + af * 4];
            #pragma unroll
            for (int q = 0; q < 8; q++) rA[q] = *(const float4*)(p + q * 4);
            #pragma unroll
            for (int t = 0; t < 4; t++) {
                int i = tid + t * 256;
                int r = (i >> 3) & 127, seg = i & 7;
                cpa16(sbase + nb * STAGE + BHI + r * RS + seg * 16,
                      g_Wh + (size_t)(n0 + r) * HH + (c + 1) * BK + seg * 8);
            }
            asm volatile("cp.async.commit_group;" ::: "memory");
        }

        // ---- compute on buffer pb ----
        {
            const uint32_t st = sbase + pb * STAGE;
            #pragma unroll
            for (int ks = 0; ks < 4; ks++) {
                const uint32_t kso = (uint32_t)(ks * 32);
                uint32_t bh[4][2];
                ldsm4(bh[0][0], bh[0][1], bh[1][0], bh[1][1], st + BHI + boff + kso);
                ldsm4(bh[2][0], bh[2][1], bh[3][0], bh[3][1], st + BHI + boff + kso + 16 * RS);
                #pragma unroll
                for (int mi = 0; mi < 4; mi++) {
                    uint32_t ah[4];
                    const uint32_t am = aoff + (uint32_t)(mi * 16 * RS) + kso;
                    ldsm4(ah[0], ah[1], ah[2], ah[3], st + AHI + am);
                    #pragma unroll
                    for (int ni = 0; ni < 4; ni++)
                        mma_f16(acc[mi][ni], ah, bh[ni]);
                }
            }
        }

        if (c + 1 < NKC) {
            #pragma unroll
            for (int q = 0; q < 8; q++) {
                float4 v = rA[q];
                uint2 hp = make_uint2(pack_h2(v.x, v.y), pack_h2(v.z, v.w));
                *(uint2*)(sm + nb * STAGE + AHI + arow * RS + (af + q) * 8) = hp;
            }
            asm volatile("cp.async.wait_group 0;" ::: "memory");
            __syncthreads();
        }
    }

    // ---- epilogue: tanh(z + b) * w, reduced over this CTA's 128 columns ----
    float* red = (float*)(sm + REDOFF);
    #pragma unroll
    for (int mi = 0; mi < 4; mi++) {
        float s0 = 0.f, s1 = 0.f;
        #pragma unroll
        for (int ni = 0; ni < 4; ni++) {
            int col = n0 + wn * 32 + ni * 8 + tig * 2;
            float2 bb = *(const float2*)&bias[col];
            float2 ww = *(const float2*)&wat[col];
            s0 += tanhf(acc[mi][ni][0] + bb.x) * ww.x
                + tanhf(acc[mi][ni][1] + bb.y) * ww.y;
            s1 += tanhf(acc[mi][ni][2] + bb.x) * ww.x
                + tanhf(acc[mi][ni][3] + bb.y) * ww.y;
        }
        s0 += __shfl_down_sync(0xFFFFFFFFu, s0, 2, 4);
        s0 += __shfl_down_sync(0xFFFFFFFFu, s0, 1, 4);
        s1 += __shfl_down_sync(0xFFFFFFFFu, s1, 2, 4);
        s1 += __shfl_down_sync(0xFFFFFFFFu, s1, 1, 4);
        if (tig == 0) {
            red[(wm * 64 + mi * 16 + g) * 4 + wn]     = s0;
            red[(wm * 64 + mi * 16 + 8 + g) * 4 + wn] = s1;
        }
    }
    __syncthreads();
    if (tid < 128) {
        float v = red[tid * 4] + red[tid * 4 + 1] + red[tid * 4 + 2] + red[tid * 4 + 3];
        g_part[(size_t)blockIdx.x * MM + m0 + tid] = v;
    }
}

// ---------------------------------------------------------------------------
// softmax over full sequence, then mask + renormalize.
// ---------------------------------------------------------------------------
__global__ __launch_bounds__(256) void softmax_kernel(const int* __restrict__ seqlen)
{
    __shared__ float sc[SS];
    __shared__ float red[256];
    __shared__ float red2[256];

    const int b = blockIdx.x, tid = threadIdx.x;
    const int len = seqlen[b];

    for (int s = tid; s < SS; s += 256) {
        float v = 0.f;
        #pragma unroll
        for (int j = 0; j < NT; j++)
            v += g_part[(size_t)j * MM + (size_t)b * SS + s];
        sc[s] = v;
    }
    __syncthreads();

    float m = -INFINITY;
    for (int s = tid; s < SS; s += 256) m = fmaxf(m, sc[s]);
    red[tid] = m;
    __syncthreads();
    for (int o = 128; o > 0; o >>= 1) {
        if (tid < o) red[tid] = fmaxf(red[tid], red[tid + o]);
        __syncthreads();
    }
    m = red[0];
    __syncthreads();

    float z = 0.f, zm = 0.f;
    for (int s = tid; s < SS; s += 256) {
        float e = expf(sc[s] - m);
        z += e;
        if (s < len) zm += e;
    }
    red[tid] = z; red2[tid] = zm;
    __syncthreads();
    for (int o = 128; o > 0; o >>= 1) {
        if (tid < o) { red[tid] += red[tid + o]; red2[tid] += red2[tid + o]; }
        __syncthreads();
    }
    z = red[0]; zm = red2[0];

    const float inv = 1.f / (zm + 1e-6f * z);
    for (int s = tid; s < SS; s += 256) {
        float e = (s < len) ? expf(sc[s] - m) * inv : 0.f;
        g_attn[(size_t)b * SS + s] = e;
    }
}

// ---------------------------------------------------------------------------
// pooling partials (4 independent accumulators) + reduce
// ---------------------------------------------------------------------------
__global__ __launch_bounds__(HH) void pool_kernel(
    const float* __restrict__ X, const int* __restrict__ seqlen)
{
    const int b = blockIdx.x, c = blockIdx.y, h = threadIdx.x;
    const int s0 = c * SCHUNK;
    const int len = seqlen[b];

    __shared__ float at[SCHUNK];
    if (h < SCHUNK) at[h] = g_attn[(size_t)b * SS + s0 + h];
    __syncthreads();

    int end = len - s0;
    if (end > SCHUNK) end = SCHUNK;
    float a0 = 0.f, a1 = 0.f, a2 = 0.f, a3 = 0.f;
    if (end > 0) {
        const float* xp = &X[((size_t)b * SS + s0) * HH + h];
        int s = 0;
        for (; s + 3 < end; s += 4) {
            a0 = fmaf(xp[(size_t)(s + 0) * HH], at[s + 0], a0);
            a1 = fmaf(xp[(size_t)(s + 1) * HH], at[s + 1], a1);
            a2 = fmaf(xp[(size_t)(s + 2) * HH], at[s + 2], a2);
            a3 = fmaf(xp[(size_t)(s + 3) * HH], at[s + 3], a3);
        }
        for (; s < end; s++)
            a0 = fmaf(xp[(size_t)s * HH], at[s], a0);
    }
    g_pout[((size_t)b * NCHUNK + c) * HH + h] = (a0 + a1) + (a2 + a3);
}

__global__ __launch_bounds__(256) void reduce_out_kernel(float* __restrict__ out)
{
    int i = blockIdx.x * blockDim.x + threadIdx.x;
    if (i >= BB * HH) return;
    int b = i / HH, h = i % HH;
    float v = 0.f;
    #pragma unroll
    for (int c = 0; c < NCHUNK; c++)
        v += g_pout[((size_t)b * NCHUNK + c) * HH + h];
    out[i] = v;
}

// ---------------------------------------------------------------------------
extern "C" void kernel_launch(void* const* d_in, const int* in_sizes, int n_in,
                              void* d_out, int out_size)
{
    const float* X      = (const float*)d_in[0];
    const int*   seqlen = (const int*)  d_in[1];
    const float* W      = (const float*)d_in[2];
    const float* bias   = (const float*)d_in[3];
    const float* wat    = (const float*)d_in[4];
    float*       out    = (float*)d_out;

    cudaFuncSetAttribute(gemm_score_mma,
                         cudaFuncAttributeMaxDynamicSharedMemorySize, SMTOTAL);

    prep_w<<<dim3(16, 16), dim3(32, 8)>>>(W);

    dim3 ggemm(NT, MM / BM);                 // (4, 1024)
    gemm_score_mma<<<ggemm, 256, SMTOTAL>>>(X, bias, wat);

    softmax_kernel<<<BB, 256>>>(seqlen);

    dim3 gpool(BB, NCHUNK);                  // (64, 16)
    pool_kernel<<<gpool, HH>>>(X, seqlen);

    reduce_out_kernel<<<(BB * HH + 255) / 256, 256>>>(out);
}

// round 7
// speedup vs baseline: 4.7837x; 1.7578x over previous
#include <cuda_runtime.h>
#include <cuda_fp16.h>
#include <math.h>
#include <stdint.h>

// ---------------- problem constants ----------------
#define BB 64
#define SS 2048
#define HH 512
#define MM (BB * SS)            // 131072 rows
#define BM 64
#define BN 256
#define BK 64
#define NKC (HH / BK)           // 8 k-chunks
#define NT  (HH / BN)           // 2 n-tiles

#define SCHUNK 128
#define NCHUNK (SS / SCHUNK)    // 16

// SMEM layout (bytes). Rows padded to 144 B -> conflict-free ldmatrix phases.
#define RS    144
#define AOFF  0
#define BOFF  (BM * RS)             // 9216
#define STAGE ((BM + BN) * RS)      // 46080
#define REDOFF (2 * STAGE)          // 92160
#define SMTOTAL (REDOFF + BM * 8 * 4)   // 94208

// ---------------- scratch (static device mem) ----------------
__device__ float g_part[NT * MM];
__device__ float g_attn[MM];
__device__ float g_pout[BB * NCHUNK * HH];
__device__ __half g_Wh[HH * HH];    // Wt[n,k] = fp16(W[k,n])
__device__ __half g_Ah[(size_t)MM * HH];  // fp16(X), 128 MB

// ---------------- helpers ----------------
__device__ __forceinline__ uint32_t smem_u32(const void* p) {
    uint32_t a;
    asm("{ .reg .u64 t; cvta.to.shared.u64 t, %1; cvt.u32.u64 %0, t; }"
        : "=r"(a) : "l"(p));
    return a;
}
__device__ __forceinline__ void cpa16(uint32_t dst, const void* src) {
    asm volatile("cp.async.cg.shared.global [%0], [%1], 16;"
                 :: "r"(dst), "l"(src) : "memory");
}
__device__ __forceinline__ void mma_f16(float* d, const uint32_t* a, const uint32_t* b) {
    asm volatile("mma.sync.aligned.m16n8k16.row.col.f32.f16.f16.f32 "
                 "{%0,%1,%2,%3}, {%4,%5,%6,%7}, {%8,%9}, {%0,%1,%2,%3};"
                 : "+f"(d[0]), "+f"(d[1]), "+f"(d[2]), "+f"(d[3])
                 : "r"(a[0]), "r"(a[1]), "r"(a[2]), "r"(a[3]),
                   "r"(b[0]), "r"(b[1]));
}
__device__ __forceinline__ void ldsm4(uint32_t& r0, uint32_t& r1, uint32_t& r2,
                                      uint32_t& r3, uint32_t addr) {
    asm volatile("ldmatrix.sync.aligned.m8n8.x4.shared.b16 {%0,%1,%2,%3}, [%4];"
                 : "=r"(r0), "=r"(r1), "=r"(r2), "=r"(r3) : "r"(addr));
}

// ---------------------------------------------------------------------------
// X prep: fp32 -> fp16, streaming.
// ---------------------------------------------------------------------------
__global__ __launch_bounds__(256) void prep_x(const float* __restrict__ X) {
    size_t i = (size_t)blockIdx.x * 256 + threadIdx.x;   // one float4 each
    float4 v = *(const float4*)(X + i * 4);
    __half2 h01 = __floats2half2_rn(v.x, v.y);
    __half2 h23 = __floats2half2_rn(v.z, v.w);
    uint2 o = make_uint2(*(uint32_t*)&h01, *(uint32_t*)&h23);
    *(uint2*)(g_Ah + i * 4) = o;
}

// ---------------------------------------------------------------------------
// W prep: transpose + fp16 round.  Wt[n,k] = fp16(W[k,n])
// ---------------------------------------------------------------------------
__global__ void prep_w(const float* __restrict__ W) {
    __shared__ float t[32][33];
    int n0 = blockIdx.x * 32, k0 = blockIdx.y * 32;
    int tx = threadIdx.x, ty = threadIdx.y;      // 32 x 8
    #pragma unroll
    for (int r = 0; r < 32; r += 8)
        t[ty + r][tx] = W[(size_t)(k0 + ty + r) * HH + n0 + tx];
    __syncthreads();
    #pragma unroll
    for (int r = 0; r < 32; r += 8) {
        int n = n0 + ty + r, k = k0 + tx;
        g_Wh[(size_t)n * HH + k] = __float2half_rn(t[tx][ty + r]);
    }
}

// ---------------------------------------------------------------------------
// fp16 HMMA GEMM, all-cp.async operands, BM=64 x BN=256, BK=64.
// grid (NT, MM/BM) = (2, 2048), 256 threads (8 warps, warp tile 64x32), 2 CTAs/SM.
// ---------------------------------------------------------------------------
__global__ __launch_bounds__(256, 2) void gemm_score_mma(
    const float* __restrict__ bias, const float* __restrict__ wat)
{
    extern __shared__ char sm[];
    const uint32_t sbase = smem_u32(sm);
    const int tid = threadIdx.x, lane = tid & 31, wid = tid >> 5;
    const int g = lane >> 2, tig = lane & 3;
    const int wn = wid;                     // 8 warps across N
    const int m0 = blockIdx.y * BM, n0 = blockIdx.x * BN;

    // ldmatrix lane-address offsets (within a stage)
    const uint32_t boff = (uint32_t)(BOFF + (wn * 32 + ((lane >> 4) * 8) + (lane & 7)) * RS
                                     + (((lane >> 3) & 1) * 16));
    const uint32_t aoff = (uint32_t)(AOFF + ((((lane >> 3) & 1) * 8) + (lane & 7)) * RS
                                     + ((lane >> 4) * 16));

    float acc[4][4][4] = {};   // [mi][ni][frag]

    // fill helper indices: 2560 segments of 16B per stage, 10 per thread
    // i < 512  -> A: r=i>>3 (0..63), seg=i&7
    // i >= 512 -> B: j=i-512, r=j>>3 (0..255), seg=j&7
    auto fill = [&](int c, uint32_t st) {
        const int k0 = c * BK;
        #pragma unroll
        for (int t = 0; t < 10; t++) {
            int i = tid + t * 256;
            if (i < 512) {
                int r = i >> 3, seg = i & 7;
                cpa16(st + AOFF + r * RS + seg * 16,
                      g_Ah + (size_t)(m0 + r) * HH + k0 + seg * 8);
            } else {
                int j = i - 512;
                int r = j >> 3, seg = j & 7;
                cpa16(st + BOFF + r * RS + seg * 16,
                      g_Wh + (size_t)(n0 + r) * HH + k0 + seg * 8);
            }
        }
        asm volatile("cp.async.commit_group;" ::: "memory");
    };

    fill(0, sbase);
    asm volatile("cp.async.wait_group 0;" ::: "memory");
    __syncthreads();

    for (int c = 0; c < NKC; c++) {
        const int pb = c & 1, nb = pb ^ 1;
        if (c + 1 < NKC) fill(c + 1, sbase + nb * STAGE);

        const uint32_t st = sbase + pb * STAGE;
        #pragma unroll
        for (int ks = 0; ks < 4; ks++) {
            const uint32_t kso = (uint32_t)(ks * 32);
            uint32_t bh[4][2];
            ldsm4(bh[0][0], bh[0][1], bh[1][0], bh[1][1], st + boff + kso);
            ldsm4(bh[2][0], bh[2][1], bh[3][0], bh[3][1], st + boff + kso + 16 * RS);
            #pragma unroll
            for (int mi = 0; mi < 4; mi++) {
                uint32_t ah[4];
                ldsm4(ah[0], ah[1], ah[2], ah[3],
                      st + aoff + (uint32_t)(mi * 16 * RS) + kso);
                #pragma unroll
                for (int ni = 0; ni < 4; ni++)
                    mma_f16(acc[mi][ni], ah, bh[ni]);
            }
        }

        if (c + 1 < NKC) {
            asm volatile("cp.async.wait_group 0;" ::: "memory");
            __syncthreads();
        }
    }

    // ---- epilogue: tanh(z + b) * w, reduce over this CTA's 256 columns ----
    float* red = (float*)(sm + REDOFF);   // [64 rows][8 warps]
    #pragma unroll
    for (int mi = 0; mi < 4; mi++) {
        float s0 = 0.f, s1 = 0.f;
        #pragma unroll
        for (int ni = 0; ni < 4; ni++) {
            int col = n0 + wn * 32 + ni * 8 + tig * 2;
            float2 bb = *(const float2*)&bias[col];
            float2 ww = *(const float2*)&wat[col];
            s0 += tanhf(acc[mi][ni][0] + bb.x) * ww.x
                + tanhf(acc[mi][ni][1] + bb.y) * ww.y;
            s1 += tanhf(acc[mi][ni][2] + bb.x) * ww.x
                + tanhf(acc[mi][ni][3] + bb.y) * ww.y;
        }
        s0 += __shfl_down_sync(0xFFFFFFFFu, s0, 2, 4);
        s0 += __shfl_down_sync(0xFFFFFFFFu, s0, 1, 4);
        s1 += __shfl_down_sync(0xFFFFFFFFu, s1, 2, 4);
        s1 += __shfl_down_sync(0xFFFFFFFFu, s1, 1, 4);
        if (tig == 0) {
            red[(mi * 16 + g) * 8 + wn]     = s0;
            red[(mi * 16 + 8 + g) * 8 + wn] = s1;
        }
    }
    __syncthreads();
    if (tid < BM) {
        const float* r = red + tid * 8;
        float v = ((r[0] + r[1]) + (r[2] + r[3])) + ((r[4] + r[5]) + (r[6] + r[7]));
        g_part[(size_t)blockIdx.x * MM + m0 + tid] = v;
    }
}

// ---------------------------------------------------------------------------
// softmax over full sequence, then mask + renormalize.
// ---------------------------------------------------------------------------
__global__ __launch_bounds__(256) void softmax_kernel(const int* __restrict__ seqlen)
{
    __shared__ float sc[SS];
    __shared__ float red[256];
    __shared__ float red2[256];

    const int b = blockIdx.x, tid = threadIdx.x;
    const int len = seqlen[b];

    for (int s = tid; s < SS; s += 256) {
        float v = 0.f;
        #pragma unroll
        for (int j = 0; j < NT; j++)
            v += g_part[(size_t)j * MM + (size_t)b * SS + s];
        sc[s] = v;
    }
    __syncthreads();

    float m = -INFINITY;
    for (int s = tid; s < SS; s += 256) m = fmaxf(m, sc[s]);
    red[tid] = m;
    __syncthreads();
    for (int o = 128; o > 0; o >>= 1) {
        if (tid < o) red[tid] = fmaxf(red[tid], red[tid + o]);
        __syncthreads();
    }
    m = red[0];
    __syncthreads();

    float z = 0.f, zm = 0.f;
    for (int s = tid; s < SS; s += 256) {
        float e = expf(sc[s] - m);
        z += e;
        if (s < len) zm += e;
    }
    red[tid] = z; red2[tid] = zm;
    __syncthreads();
    for (int o = 128; o > 0; o >>= 1) {
        if (tid < o) { red[tid] += red[tid + o]; red2[tid] += red2[tid + o]; }
        __syncthreads();
    }
    z = red[0]; zm = red2[0];

    const float inv = 1.f / (zm + 1e-6f * z);
    for (int s = tid; s < SS; s += 256) {
        float e = (s < len) ? expf(sc[s] - m) * inv : 0.f;
        g_attn[(size_t)b * SS + s] = e;
    }
}

// ---------------------------------------------------------------------------
// pooling partials (4 independent accumulators) + reduce
// ---------------------------------------------------------------------------
__global__ __launch_bounds__(HH) void pool_kernel(
    const float* __restrict__ X, const int* __restrict__ seqlen)
{
    const int b = blockIdx.x, c = blockIdx.y, h = threadIdx.x;
    const int s0 = c * SCHUNK;
    const int len = seqlen[b];

    __shared__ float at[SCHUNK];
    if (h < SCHUNK) at[h] = g_attn[(size_t)b * SS + s0 + h];
    __syncthreads();

    int end = len - s0;
    if (end > SCHUNK) end = SCHUNK;
    float a0 = 0.f, a1 = 0.f, a2 = 0.f, a3 = 0.f;
    if (end > 0) {
        const float* xp = &X[((size_t)b * SS + s0) * HH + h];
        int s = 0;
        for (; s + 3 < end; s += 4) {
            a0 = fmaf(xp[(size_t)(s + 0) * HH], at[s + 0], a0);
            a1 = fmaf(xp[(size_t)(s + 1) * HH], at[s + 1], a1);
            a2 = fmaf(xp[(size_t)(s + 2) * HH], at[s + 2], a2);
            a3 = fmaf(xp[(size_t)(s + 3) * HH], at[s + 3], a3);
        }
        for (; s < end; s++)
            a0 = fmaf(xp[(size_t)s * HH], at[s], a0);
    }
    g_pout[((size_t)b * NCHUNK + c) * HH + h] = (a0 + a1) + (a2 + a3);
}

__global__ __launch_bounds__(256) void reduce_out_kernel(float* __restrict__ out)
{
    int i = blockIdx.x * blockDim.x + threadIdx.x;
    if (i >= BB * HH) return;
    int b = i / HH, h = i % HH;
    float v = 0.f;
    #pragma unroll
    for (int c = 0; c < NCHUNK; c++)
        v += g_pout[((size_t)b * NCHUNK + c) * HH + h];
    out[i] = v;
}

// ---------------------------------------------------------------------------
extern "C" void kernel_launch(void* const* d_in, const int* in_sizes, int n_in,
                              void* d_out, int out_size)
{
    const float* X      = (const float*)d_in[0];
    const int*   seqlen = (const int*)  d_in[1];
    const float* W      = (const float*)d_in[2];
    const float* bias   = (const float*)d_in[3];
    const float* wat    = (const float*)d_in[4];
    float*       out    = (float*)d_out;

    cudaFuncSetAttribute(gemm_score_mma,
                         cudaFuncAttributeMaxDynamicSharedMemorySize, SMTOTAL);

    prep_w<<<dim3(16, 16), dim3(32, 8)>>>(W);
    prep_x<<<(int)((size_t)MM * HH / 4 / 256), 256>>>(X);

    dim3 ggemm(NT, MM / BM);                 // (2, 2048)
    gemm_score_mma<<<ggemm, 256, SMTOTAL>>>(bias, wat);

    softmax_kernel<<<BB, 256>>>(seqlen);

    dim3 gpool(BB, NCHUNK);                  // (64, 16)
    pool_kernel<<<gpool, HH>>>(X, seqlen);

    reduce_out_kernel<<<(BB * HH + 255) / 256, 256>>>(out);
}

// round 8
// speedup vs baseline: 5.0845x; 1.0629x over previous
#include <cuda_runtime.h>
#include <cuda_fp16.h>
#include <math.h>
#include <stdint.h>

// ---------------- problem constants ----------------
#define BB 64
#define SS 2048
#define HH 512
#define MM (BB * SS)            // 131072 rows
#define BM 64
#define BN 512
#define BK 64
#define NKC (HH / BK)           // 8 k-chunks

#define SCHUNK 128
#define NCHUNK (SS / SCHUNK)    // 16

// SMEM layout (bytes). Rows padded to 144 B -> conflict-free ldmatrix phases.
#define RS    144
#define AOFF  0
#define BOFF  (BM * RS)             // 9216
#define STAGE ((BM + BN) * RS)      // 82944
#define REDOFF (2 * STAGE)          // 165888
#define SMTOTAL (REDOFF + BM * 16 * 4)  // 169984

// ---------------- scratch (static device mem) ----------------
__device__ float g_part[MM];
__device__ float g_attn[MM];
__device__ float g_pout[BB * NCHUNK * HH];
__device__ __half g_Wh[HH * HH];    // Wt[n,k] = fp16(W[k,n])

// ---------------- helpers ----------------
__device__ __forceinline__ uint32_t smem_u32(const void* p) {
    uint32_t a;
    asm("{ .reg .u64 t; cvta.to.shared.u64 t, %1; cvt.u32.u64 %0, t; }"
        : "=r"(a) : "l"(p));
    return a;
}
__device__ __forceinline__ void cpa16(uint32_t dst, const void* src) {
    asm volatile("cp.async.cg.shared.global [%0], [%1], 16;"
                 :: "r"(dst), "l"(src) : "memory");
}
__device__ __forceinline__ void mma_f16(float* d, const uint32_t* a, const uint32_t* b) {
    asm volatile("mma.sync.aligned.m16n8k16.row.col.f32.f16.f16.f32 "
                 "{%0,%1,%2,%3}, {%4,%5,%6,%7}, {%8,%9}, {%0,%1,%2,%3};"
                 : "+f"(d[0]), "+f"(d[1]), "+f"(d[2]), "+f"(d[3])
                 : "r"(a[0]), "r"(a[1]), "r"(a[2]), "r"(a[3]),
                   "r"(b[0]), "r"(b[1]));
}
__device__ __forceinline__ void ldsm4(uint32_t& r0, uint32_t& r1, uint32_t& r2,
                                      uint32_t& r3, uint32_t addr) {
    asm volatile("ldmatrix.sync.aligned.m8n8.x4.shared.b16 {%0,%1,%2,%3}, [%4];"
                 : "=r"(r0), "=r"(r1), "=r"(r2), "=r"(r3) : "r"(addr));
}
__device__ __forceinline__ uint32_t pack_h2(float x, float y) {
    __half2 h = __floats2half2_rn(x, y);
    return *(uint32_t*)&h;
}

// ---------------------------------------------------------------------------
// W prep: transpose + fp16 round.  Wt[n,k] = fp16(W[k,n])
// ---------------------------------------------------------------------------
__global__ void prep_w(const float* __restrict__ W) {
    __shared__ float t[32][33];
    int n0 = blockIdx.x * 32, k0 = blockIdx.y * 32;
    int tx = threadIdx.x, ty = threadIdx.y;      // 32 x 8
    #pragma unroll
    for (int r = 0; r < 32; r += 8)
        t[ty + r][tx] = W[(size_t)(k0 + ty + r) * HH + n0 + tx];
    __syncthreads();
    #pragma unroll
    for (int r = 0; r < 32; r += 8) {
        int n = n0 + ty + r, k = k0 + tx;
        g_Wh[(size_t)n * HH + k] = __float2half_rn(t[tx][ty + r]);
    }
}

// ---------------------------------------------------------------------------
// fp16 HMMA GEMM, single N-pass (BN=512). X read fp32 ONCE, cvt in-register.
// grid (MM/BM) = 2048, 512 threads (16 warps across N, warp tile 64x32).
// ---------------------------------------------------------------------------
__global__ __launch_bounds__(512, 1) void gemm_score_mma(
    const float* __restrict__ A, const float* __restrict__ bias,
    const float* __restrict__ wat)
{
    extern __shared__ char sm[];
    const uint32_t sbase = smem_u32(sm);
    const int tid = threadIdx.x, lane = tid & 31, wid = tid >> 5;
    const int g = lane >> 2, tig = lane & 3;
    const int wn = wid;                     // 16 warps across N
    const int m0 = blockIdx.x * BM;

    // A fill mapping: r = tid>>3 (0..63), seg = tid&7 (0..7) -> 8 floats
    const int ar = tid >> 3, aseg = tid & 7;

    // ldmatrix lane-address offsets (within a stage)
    const uint32_t boff = (uint32_t)(BOFF + (wn * 32 + ((lane >> 4) * 8) + (lane & 7)) * RS
                                     + (((lane >> 3) & 1) * 16));
    const uint32_t aoff = (uint32_t)(AOFF + ((((lane >> 3) & 1) * 8) + (lane & 7)) * RS
                                     + ((lane >> 4) * 16));

    float acc[4][4][4] = {};   // [mi][ni][frag]

    // fill: A (fp32 load + cvt + STS), B (cp.async), one chunk into stage st
    auto fill = [&](int c, uint32_t st) {
        const int k0 = c * BK;
        // B: 512 rows x 8 segs = 4096 cp.async / 512 threads = 8 each
        #pragma unroll
        for (int t = 0; t < 8; t++) {
            int i = tid + t * 512;
            int r = i >> 3, seg = i & 7;
            cpa16(st + BOFF + r * RS + seg * 16,
                  g_Wh + (size_t)r * HH + k0 + seg * 8);
        }
        asm volatile("cp.async.commit_group;" ::: "memory");
        // A: 64 rows x 64 k fp32 -> fp16
        const float* p = &A[(size_t)(m0 + ar) * HH + k0 + aseg * 8];
        float4 v0 = *(const float4*)p;
        float4 v1 = *(const float4*)(p + 4);
        uint4 hp = make_uint4(pack_h2(v0.x, v0.y), pack_h2(v0.z, v0.w),
                              pack_h2(v1.x, v1.y), pack_h2(v1.z, v1.w));
        *(uint4*)(sm + (st - sbase) + AOFF + ar * RS + aseg * 16) = hp;
    };

    fill(0, sbase);
    asm volatile("cp.async.wait_group 0;" ::: "memory");
    __syncthreads();

    for (int c = 0; c < NKC; c++) {
        const int pb = c & 1, nb = pb ^ 1;
        if (c + 1 < NKC) fill(c + 1, sbase + nb * STAGE);

        const uint32_t st = sbase + pb * STAGE;
        #pragma unroll
        for (int ks = 0; ks < 4; ks++) {
            const uint32_t kso = (uint32_t)(ks * 32);
            uint32_t bh[4][2];
            ldsm4(bh[0][0], bh[0][1], bh[1][0], bh[1][1], st + boff + kso);
            ldsm4(bh[2][0], bh[2][1], bh[3][0], bh[3][1], st + boff + kso + 16 * RS);
            #pragma unroll
            for (int mi = 0; mi < 4; mi++) {
                uint32_t ah[4];
                ldsm4(ah[0], ah[1], ah[2], ah[3],
                      st + aoff + (uint32_t)(mi * 16 * RS) + kso);
                #pragma unroll
                for (int ni = 0; ni < 4; ni++)
                    mma_f16(acc[mi][ni], ah, bh[ni]);
            }
        }

        if (c + 1 < NKC) {
            asm volatile("cp.async.wait_group 0;" ::: "memory");
            __syncthreads();
        }
    }

    // ---- epilogue: tanh(z + b) * w, reduce over ALL 512 columns ----
    float* red = (float*)(sm + REDOFF);   // [64 rows][16 warps]
    #pragma unroll
    for (int mi = 0; mi < 4; mi++) {
        float s0 = 0.f, s1 = 0.f;
        #pragma unroll
        for (int ni = 0; ni < 4; ni++) {
            int col = wn * 32 + ni * 8 + tig * 2;
            float2 bb = *(const float2*)&bias[col];
            float2 ww = *(const float2*)&wat[col];
            s0 += tanhf(acc[mi][ni][0] + bb.x) * ww.x
                + tanhf(acc[mi][ni][1] + bb.y) * ww.y;
            s1 += tanhf(acc[mi][ni][2] + bb.x) * ww.x
                + tanhf(acc[mi][ni][3] + bb.y) * ww.y;
        }
        s0 += __shfl_down_sync(0xFFFFFFFFu, s0, 2, 4);
        s0 += __shfl_down_sync(0xFFFFFFFFu, s0, 1, 4);
        s1 += __shfl_down_sync(0xFFFFFFFFu, s1, 2, 4);
        s1 += __shfl_down_sync(0xFFFFFFFFu, s1, 1, 4);
        if (tig == 0) {
            red[(mi * 16 + g) * 16 + wn]     = s0;
            red[(mi * 16 + 8 + g) * 16 + wn] = s1;
        }
    }
    __syncthreads();
    if (tid < BM) {
        const float* r = red + tid * 16;
        float v = 0.f;
        #pragma unroll
        for (int j = 0; j < 16; j++) v += r[j];
        g_part[(size_t)m0 + tid] = v;
    }
}

// ---------------------------------------------------------------------------
// softmax over full sequence, then mask + renormalize.
// ---------------------------------------------------------------------------
__global__ __launch_bounds__(256) void softmax_kernel(const int* __restrict__ seqlen)
{
    __shared__ float sc[SS];
    __shared__ float red[256];
    __shared__ float red2[256];

    const int b = blockIdx.x, tid = threadIdx.x;
    const int len = seqlen[b];

    for (int s = tid; s < SS; s += 256)
        sc[s] = g_part[(size_t)b * SS + s];
    __syncthreads();

    float m = -INFINITY;
    for (int s = tid; s < SS; s += 256) m = fmaxf(m, sc[s]);
    red[tid] = m;
    __syncthreads();
    for (int o = 128; o > 0; o >>= 1) {
        if (tid < o) red[tid] = fmaxf(red[tid], red[tid + o]);
        __syncthreads();
    }
    m = red[0];
    __syncthreads();

    float z = 0.f, zm = 0.f;
    for (int s = tid; s < SS; s += 256) {
        float e = expf(sc[s] - m);
        z += e;
        if (s < len) zm += e;
    }
    red[tid] = z; red2[tid] = zm;
    __syncthreads();
    for (int o = 128; o > 0; o >>= 1) {
        if (tid < o) { red[tid] += red[tid + o]; red2[tid] += red2[tid + o]; }
        __syncthreads();
    }
    z = red[0]; zm = red2[0];

    const float inv = 1.f / (zm + 1e-6f * z);
    for (int s = tid; s < SS; s += 256) {
        float e = (s < len) ? expf(sc[s] - m) * inv : 0.f;
        g_attn[(size_t)b * SS + s] = e;
    }
}

// ---------------------------------------------------------------------------
// pooling partials (4 independent accumulators) + reduce
// ---------------------------------------------------------------------------
__global__ __launch_bounds__(HH) void pool_kernel(
    const float* __restrict__ X, const int* __restrict__ seqlen)
{
    const int b = blockIdx.x, c = blockIdx.y, h = threadIdx.x;
    const int s0 = c * SCHUNK;
    const int len = seqlen[b];

    __shared__ float at[SCHUNK];
    if (h < SCHUNK) at[h] = g_attn[(size_t)b * SS + s0 + h];
    __syncthreads();

    int end = len - s0;
    if (end > SCHUNK) end = SCHUNK;
    float a0 = 0.f, a1 = 0.f, a2 = 0.f, a3 = 0.f;
    if (end > 0) {
        const float* xp = &X[((size_t)b * SS + s0) * HH + h];
        int s = 0;
        for (; s + 3 < end; s += 4) {
            a0 = fmaf(xp[(size_t)(s + 0) * HH], at[s + 0], a0);
            a1 = fmaf(xp[(size_t)(s + 1) * HH], at[s + 1], a1);
            a2 = fmaf(xp[(size_t)(s + 2) * HH], at[s + 2], a2);
            a3 = fmaf(xp[(size_t)(s + 3) * HH], at[s + 3], a3);
        }
        for (; s < end; s++)
            a0 = fmaf(xp[(size_t)s * HH], at[s], a0);
    }
    g_pout[((size_t)b * NCHUNK + c) * HH + h] = (a0 + a1) + (a2 + a3);
}

__global__ __launch_bounds__(256) void reduce_out_kernel(float* __restrict__ out)
{
    int i = blockIdx.x * blockDim.x + threadIdx.x;
    if (i >= BB * HH) return;
    int b = i / HH, h = i % HH;
    float v = 0.f;
    #pragma unroll
    for (int c = 0; c < NCHUNK; c++)
        v += g_pout[((size_t)b * NCHUNK + c) * HH + h];
    out[i] = v;
}

// ---------------------------------------------------------------------------
extern "C" void kernel_launch(void* const* d_in, const int* in_sizes, int n_in,
                              void* d_out, int out_size)
{
    const float* X      = (const float*)d_in[0];
    const int*   seqlen = (const int*)  d_in[1];
    const float* W      = (const float*)d_in[2];
    const float* bias   = (const float*)d_in[3];
    const float* wat    = (const float*)d_in[4];
    float*       out    = (float*)d_out;

    cudaFuncSetAttribute(gemm_score_mma,
                         cudaFuncAttributeMaxDynamicSharedMemorySize, SMTOTAL);

    prep_w<<<dim3(16, 16), dim3(32, 8)>>>(W);

    gemm_score_mma<<<MM / BM, 512, SMTOTAL>>>(X, bias, wat);

    softmax_kernel<<<BB, 256>>>(seqlen);

    dim3 gpool(BB, NCHUNK);                  // (64, 16)
    pool_kernel<<<gpool, HH>>>(X, seqlen);

    reduce_out_kernel<<<(BB * HH + 255) / 256, 256>>>(out);
}